// round 14
// baseline (speedup 1.0000x reference)
#include <cuda_runtime.h>
#include <cstdint>

#define B_  4
#define T_  1024
#define TT  2048
#define D_  512
#define H_  8
#define HD  64

// Scratch (allocation-free rule: __device__ globals).
__device__ float g_Q[B_*H_*TT*HD];     // tf32 (b,h,pos,hd), pos = time-sorted
__device__ float g_K[B_*H_*TT*HD];     // tf32 (b,h,pos,hd), hd ilv8, sorted
__device__ float g_Vt[B_*H_*HD*TT];    // tf32 V^T (b,h,hd,pos), pos ilv8, sorted
__device__ float g_Y[B_*TT*D_];        // attn out, tf32, (b,t,d) ORIGINAL order
__device__ float g_rXs[B_*T_*D_];      // tf32, k ilv8
__device__ float g_rXc[B_*T_*D_];
__device__ float g_WsT[3*D_*D_];       // W^T (n,k), tf32, k ilv8
__device__ float g_WcT[3*D_*D_];
__device__ float g_WpT[D_*D_];
// time-sort outputs
__device__ int g_sortT[B_*TT];         // sorted times, ascending
__device__ int g_perm[B_*TT];          // sorted pos -> original index
__device__ int g_rank[B_*TT];          // original index -> sorted pos

__device__ __forceinline__ uint32_t f2tf32(float x) {
    uint32_t r;
    asm("cvt.rna.tf32.f32 %0, %1;" : "=r"(r) : "f"(x));
    return r;
}
__device__ __forceinline__ float fexp2(float x) {
    float y;
    asm("ex2.approx.f32 %0, %1;" : "=f"(y) : "f"(x));
    return y;
}
__device__ __forceinline__ int ilv8(int k) {
    return (k & ~7) | ((k & 3) << 1) | ((k & 4) >> 2);
}
__device__ __forceinline__ void mma16n8k8(float* c, const uint32_t* a,
                                          uint32_t b0, uint32_t b1) {
    asm volatile(
        "mma.sync.aligned.m16n8k8.row.col.f32.tf32.tf32.f32 "
        "{%0,%1,%2,%3}, {%4,%5,%6,%7}, {%8,%9}, {%0,%1,%2,%3};"
        : "+f"(c[0]), "+f"(c[1]), "+f"(c[2]), "+f"(c[3])
        : "r"(a[0]), "r"(a[1]), "r"(a[2]), "r"(a[3]), "r"(b0), "r"(b1));
}
__device__ __forceinline__ void cp16(uint32_t dst, const void* src) {
    asm volatile("cp.async.cg.shared.global [%0], [%1], 16;"
                 :: "r"(dst), "l"(src) : "memory");
}
#define CP_COMMIT() asm volatile("cp.async.commit_group;" ::: "memory")
#define CP_WAIT(n)  asm volatile("cp.async.wait_group %0;" :: "n"(n) : "memory")
__device__ __forceinline__ uint32_t smem_u32(const void* p) {
    uint32_t a;
    asm("{ .reg .u64 t; cvta.to.shared.u64 t, %1; cvt.u32.u64 %0, t; }"
        : "=r"(a) : "l"(p));
    return a;
}

// ============================================================================
// Time sort: per batch, bitonic sort of 2048 (t, idx) pairs (deterministic).
// ============================================================================
__global__ __launch_bounds__(256) void sort_time(
    const int* __restrict__ t_self, const int* __restrict__ t_cross)
{
    __shared__ int st[2048];
    __shared__ int sp[2048];
    const int b = blockIdx.x;
    const int tid = threadIdx.x;

    for (int i = tid; i < 2048; i += 256) {
        st[i] = (i < T_) ? t_self[b*T_ + i] : t_cross[b*T_ + i - T_];
        sp[i] = i;
    }
    __syncthreads();

    for (int k = 2; k <= 2048; k <<= 1) {
        for (int j = k >> 1; j > 0; j >>= 1) {
            for (int i = tid; i < 2048; i += 256) {
                int ixj = i ^ j;
                if (ixj > i) {
                    bool up = ((i & k) == 0);
                    int t1 = st[i], t2 = st[ixj];
                    int p1 = sp[i], p2 = sp[ixj];
                    bool gt = (t1 > t2) || (t1 == t2 && p1 > p2);
                    if (gt == up) {
                        st[i] = t2; st[ixj] = t1;
                        sp[i] = p2; sp[ixj] = p1;
                    }
                }
            }
            __syncthreads();
        }
    }
    for (int i = tid; i < 2048; i += 256) {
        g_sortT[b*TT + i] = st[i];
        g_perm[b*TT + i]  = sp[i];
        g_rank[b*TT + sp[i]] = i;
    }
}

// ============================================================================
// Pre-pass: round X to tf32 + k-interleave.
// ============================================================================
#define NX8 (B_*T_*D_/8)

__global__ __launch_bounds__(256) void round_x(
    const float* __restrict__ Xs, const float* __restrict__ Xc)
{
    int i = blockIdx.x * 256 + threadIdx.x;
    if (i >= 2 * NX8) return;
    const float4* src = (i < NX8) ? (const float4*)Xs : (const float4*)Xc;
    float4* dst       = (i < NX8) ? (float4*)g_rXs    : (float4*)g_rXc;
    int j = (i < NX8) ? i : i - NX8;
    float4 a = src[2*j], b = src[2*j + 1];
    uint4 o0 = make_uint4(f2tf32(a.x), f2tf32(b.x), f2tf32(a.y), f2tf32(b.y));
    uint4 o1 = make_uint4(f2tf32(a.z), f2tf32(b.z), f2tf32(a.w), f2tf32(b.w));
    ((uint4*)dst)[2*j]     = o0;
    ((uint4*)dst)[2*j + 1] = o1;
}

// ============================================================================
// Pre-pass: transpose W (k,n)->(n,k) with tf32 rounding + k-interleave.
// ============================================================================
__global__ __launch_bounds__(256) void wt_kernel(
    const float* __restrict__ Ws, const float* __restrict__ Wc,
    const float* __restrict__ Wp)
{
    const int z = blockIdx.z;
    if (z == 2 && blockIdx.y >= 16) return;
    const float* W = (z == 0) ? Ws : (z == 1) ? Wc : Wp;
    float* WT      = (z == 0) ? g_WsT : (z == 1) ? g_WcT : g_WpT;
    const int N = (z == 2) ? 512 : 1536;

    __shared__ float sm[32][33];
    const int kb = blockIdx.x * 32;
    const int nb = blockIdx.y * 32;
    const int tid = threadIdx.x;

    #pragma unroll
    for (int i = tid; i < 1024; i += 256) {
        int r = i >> 5, c = i & 31;
        sm[r][c] = W[(size_t)(kb + r) * N + nb + c];
    }
    __syncthreads();
    #pragma unroll
    for (int i = tid; i < 1024; i += 256) {
        int nl = i >> 5, kp = i & 31;
        int klog = (kp & ~7) | ((kp & 1) << 2) | ((kp >> 1) & 3);
        WT[(size_t)(nb + nl) * 512 + kb + kp] =
            __uint_as_float(f2tf32(sm[klog][nl]));
    }
}

// ============================================================================
// QKV GEMM: epilogue scatters Q/K/V to time-sorted positions via g_rank.
// ============================================================================
#define LDA 40
#define TILEF (128*LDA)
#define SLABF (2*TILEF)
#define GEMM_SMEM (2*SLABF*4)

__global__ __launch_bounds__(256, 2) void qkv_mma(
    const float* __restrict__ bS, const float* __restrict__ bC)
{
    extern __shared__ float smf[];
    const uint32_t sbU = smem_u32(smf);

    const int z = blockIdx.z;
    const float* X    = z ? g_rXc : g_rXs;
    const float* WT   = z ? g_WcT : g_WsT;
    const float* bias = z ? bC : bS;
    const int seq_off = z ? 1024 : 0;

    const int tid  = threadIdx.x;
    const int wid  = tid >> 5, lane = tid & 31;
    const int g = lane >> 2, th = lane & 3;
    const int wm = wid & 3, wn = wid >> 2;
    const int m0 = blockIdx.y * 128, n0 = blockIdx.x * 128;

    auto stage = [&](int k0, int buf) {
        const uint32_t adst = sbU + (buf ? (uint32_t)(SLABF*4) : 0u);
        const uint32_t bdst = adst + TILEF*4;
        #pragma unroll
        for (int i = 0; i < 4; i++) {
            int cid = tid + i * 256;
            int r = cid >> 3, c = cid & 7;
            cp16(adst + (r*LDA + c*4)*4, X + (size_t)(m0 + r)*512 + k0 + c*4);
        }
        #pragma unroll
        for (int i = 0; i < 4; i++) {
            int cid = tid + i * 256;
            int r = cid >> 3, c = cid & 7;
            cp16(bdst + (r*LDA + c*4)*4, WT + (size_t)(n0 + r)*512 + k0 + c*4);
        }
        CP_COMMIT();
    };

    float acc[2][8][4];
    #pragma unroll
    for (int mt = 0; mt < 2; mt++)
        #pragma unroll
        for (int nt = 0; nt < 8; nt++)
            #pragma unroll
            for (int j = 0; j < 4; j++) acc[mt][nt][j] = 0.f;

    stage(0, 0);
    #pragma unroll 1
    for (int it = 0; it < 16; it++) {
        const int buf = it & 1;
        if (it < 15) { stage((it + 1) * 32, buf ^ 1); CP_WAIT(1); }
        else         { CP_WAIT(0); }
        __syncthreads();

        const float* As = smf + (buf ? SLABF : 0);
        const float* Bs = As + TILEF;

        #pragma unroll
        for (int s = 0; s < 4; s++) {
            uint32_t aF[2][4];
            #pragma unroll
            for (int mt = 0; mt < 2; mt++) {
                int rb = wm * 32 + mt * 16 + g;
                uint2 aLo = *(const uint2*)&As[rb * LDA + s*8 + 2*th];
                uint2 aHi = *(const uint2*)&As[(rb + 8) * LDA + s*8 + 2*th];
                aF[mt][0] = aLo.x; aF[mt][1] = aHi.x;
                aF[mt][2] = aLo.y; aF[mt][3] = aHi.y;
            }
            #pragma unroll
            for (int nt = 0; nt < 8; nt++) {
                int nc = wn * 64 + nt * 8 + g;
                uint2 bb = *(const uint2*)&Bs[nc * LDA + s*8 + 2*th];
                mma16n8k8(acc[0][nt], aF[0], bb.x, bb.y);
                mma16n8k8(acc[1][nt], aF[1], bb.x, bb.y);
            }
        }
        __syncthreads();
    }

    #pragma unroll
    for (int mt = 0; mt < 2; mt++) {
        #pragma unroll
        for (int r2 = 0; r2 < 2; r2++) {
            int row = m0 + wm * 32 + mt * 16 + g + r2 * 8;
            int bb = row >> 10;
            int tg = (row & 1023) + seq_off;
            int pos = g_rank[bb * TT + tg];          // time-sorted position
            #pragma unroll
            for (int nt = 0; nt < 8; nt++) {
                int col = n0 + wn * 64 + nt * 8 + 2 * th;
                float v0 = acc[mt][nt][r2*2+0] + bias[col];
                float v1 = acc[mt][nt][r2*2+1] + bias[col+1];
                int sel = col >> 9, c = col & 511;
                int h = c >> 6, dd = c & 63;
                if (sel == 2) {
                    int tgp = (pos & ~7) | ((pos & 3) << 1) | ((pos & 4) >> 2);
                    float* dv = g_Vt + ((((size_t)bb * H_ + h) * HD + dd) * TT) + tgp;
                    dv[0]  = __uint_as_float(f2tf32(v0));
                    dv[TT] = __uint_as_float(f2tf32(v1));
                } else if (sel == 1) {
                    size_t base = (((size_t)bb * H_ + h) * TT + pos) << 6;
                    g_K[base + ilv8(dd)]     = __uint_as_float(f2tf32(v0));
                    g_K[base + ilv8(dd + 1)] = __uint_as_float(f2tf32(v1));
                } else {
                    size_t off = ((((size_t)bb * H_ + h) * TT + pos) << 6) + dd;
                    g_Q[off]     = __uint_as_float(f2tf32(v0));
                    g_Q[off + 1] = __uint_as_float(f2tf32(v1));
                }
            }
        }
    }
}

// ============================================================================
// Flash attention on time-sorted tokens, k-loop bounded by nkt.
// 1-D grid, GLOBALLY heavy-first: qt = 15 - (blockIdx.x / 32) so all 32
// heaviest (bh) tiles launch before any lighter tier (LPT schedule; the
// per-y ordering in R13 left 32-kt tiles launching near the end = long tail).
// ============================================================================
#define KT  64
#define NKT 32
#define LDK 72
#define LDV 72
#define LDP 68
#define K0B 0
#define K1B 18432
#define V0B 36864
#define V1B 55296
#define PB  73728
#define T0B 108544
#define T1B 108800
#define ATTN_SMEM 109056

__global__ __launch_bounds__(256, 2) void attn_mma(void)
{
    extern __shared__ char smc[];
    const uint32_t sbU = smem_u32(smc);

    const int tid  = threadIdx.x;
    const int wid  = tid >> 5;
    const int lane = tid & 31;
    const int g    = lane >> 2;
    const int th   = lane & 3;
    const int qt   = 15 - (int)(blockIdx.x >> 5);   // global heavy-first
    const int bh   = (int)(blockIdx.x & 31);
    const int b    = bh >> 3, h = bh & 7;
    const int q0   = qt * 128;

    const float* Qg = g_Q + (size_t)bh * TT * HD;
    const float* Kg = g_K + (size_t)bh * TT * HD;
    const float* Vg = g_Vt + (size_t)bh * HD * TT;
    const int* sT   = g_sortT + b * TT;

    // number of live k-tiles: first j with sT[64j] > max_tq is the bound
    const int maxtq = sT[q0 + 127];
    int nkt;
    {
        bool pred = (sT[lane << 6] <= maxtq);
        nkt = __popc(__ballot_sync(0xffffffffu, pred));
    }

    auto issue = [&](int kt, int bufsel) {
        const int k0 = kt * KT;
        const uint32_t kdst = sbU + (bufsel ? K1B : K0B);
        const uint32_t vdst = sbU + (bufsel ? V1B : V0B);
        #pragma unroll
        for (int i = 0; i < 4; i++) {
            int idx = tid + i * 256;
            int row = idx >> 4, c = idx & 15;
            cp16(kdst + row * (LDK*4) + c * 16,
                 Kg + (size_t)(k0 + row) * HD + c * 4);
        }
        #pragma unroll
        for (int i = 0; i < 4; i++) {
            int idx = tid + i * 256;
            int row = idx >> 4, c = idx & 15;
            cp16(vdst + row * (LDV*4) + c * 16,
                 Vg + (size_t)row * TT + k0 + c * 4);
        }
        if (tid < 16) {
            cp16(sbU + (bufsel ? T1B : T0B) + tid * 16, sT + k0 + tid * 4);
        }
        CP_COMMIT();
    };
    issue(0, 0);

    const int wr = q0 + wid * 16;

    uint32_t aQ[8][4];
    {
        const float* qp0 = Qg + (size_t)(wr + g) * HD;
        const float* qp1 = Qg + (size_t)(wr + g + 8) * HD;
        #pragma unroll
        for (int s = 0; s < 8; s++) {
            aQ[s][0] = __float_as_uint(qp0[s*8 + th]);
            aQ[s][1] = __float_as_uint(qp1[s*8 + th]);
            aQ[s][2] = __float_as_uint(qp0[s*8 + th + 4]);
            aQ[s][3] = __float_as_uint(qp1[s*8 + th + 4]);
        }
    }
    int tq[2];
    #pragma unroll
    for (int rr = 0; rr < 2; rr++)
        tq[rr] = sT[wr + g + rr*8];

    float oacc[8][4];
    #pragma unroll
    for (int n = 0; n < 8; n++)
        #pragma unroll
        for (int j = 0; j < 4; j++) oacc[n][j] = 0.f;
    float l0 = 0.f, l1 = 0.f;

    float* Pw = (float*)(smc + PB) + wid * 16 * LDP;
    const float E = 0.125f * 1.44269504f;

    #pragma unroll 1
    for (int kt = 0; kt < nkt; kt++) {
        const int buf = kt & 1;
        if (kt < nkt - 1) { issue(kt + 1, buf ^ 1); CP_WAIT(1); }
        else              { CP_WAIT(0); }
        __syncthreads();

        const float* Ks  = (const float*)(smc + (buf ? K1B : K0B));
        const float* Vs  = (const float*)(smc + (buf ? V1B : V0B));
        const int*   tks = (const int*)(smc + (buf ? T1B : T0B));

        // ---- S = Q K^T in nb-PAIRS (two independent MMA chains) ----
        #pragma unroll
        for (int nb = 0; nb < 8; nb += 2) {
            float sa0[4] = {0.f, 0.f, 0.f, 0.f};
            float sa1[4] = {0.f, 0.f, 0.f, 0.f};
            const float* kr0 = &Ks[(nb*8 + g) * LDK];
            const float* kr1 = &Ks[((nb+1)*8 + g) * LDK];
            #pragma unroll
            for (int s = 0; s < 8; s++) {
                uint2 k0v = *(const uint2*)&kr0[s*8 + 2*th];
                uint2 k1v = *(const uint2*)&kr1[s*8 + 2*th];
                mma16n8k8(sa0, aQ[s], k0v.x, k0v.y);
                mma16n8k8(sa1, aQ[s], k1v.x, k1v.y);
            }
            #pragma unroll
            for (int u = 0; u < 2; u++) {
                const float* sa = u ? sa1 : sa0;
                const int c0 = (nb + u)*8 + 2*th;
                const int tk0 = tks[c0], tk1 = tks[c0 + 1];
                float p00 = (tq[0] >= tk0) ? fexp2(sa[0] * E) : 0.f;
                float p01 = (tq[0] >= tk1) ? fexp2(sa[1] * E) : 0.f;
                float p10 = (tq[1] >= tk0) ? fexp2(sa[2] * E) : 0.f;
                float p11 = (tq[1] >= tk1) ? fexp2(sa[3] * E) : 0.f;
                l0 += p00 + p01;  l1 += p10 + p11;
                *(uint2*)&Pw[g * LDP + c0] =
                    make_uint2(f2tf32(p00), f2tf32(p01));
                *(uint2*)&Pw[(g + 8) * LDP + c0] =
                    make_uint2(f2tf32(p10), f2tf32(p11));
            }
        }
        __syncwarp();   // P is per-warp private

        // ---- O += P V ----
        #pragma unroll
        for (int s2 = 0; s2 < 8; s2++) {
            uint32_t aP[4];
            aP[0] = __float_as_uint(Pw[g * LDP + s2*8 + th]);
            aP[1] = __float_as_uint(Pw[(g + 8) * LDP + s2*8 + th]);
            aP[2] = __float_as_uint(Pw[g * LDP + s2*8 + th + 4]);
            aP[3] = __float_as_uint(Pw[(g + 8) * LDP + s2*8 + th + 4]);
            #pragma unroll
            for (int nb2 = 0; nb2 < 8; nb2++) {
                const float* vrow = &Vs[(nb2*8 + g) * LDV];
                uint2 vb = *(const uint2*)&vrow[s2*8 + 2*th];
                mma16n8k8(oacc[nb2], aP, vb.x, vb.y);
            }
        }
        __syncthreads();   // all reads of buf done before refill
    }

    l0 += __shfl_xor_sync(0xffffffffu, l0, 1);
    l0 += __shfl_xor_sync(0xffffffffu, l0, 2);
    l1 += __shfl_xor_sync(0xffffffffu, l1, 1);
    l1 += __shfl_xor_sync(0xffffffffu, l1, 2);
    float inv[2] = {1.f / l0, 1.f / l1};

    // scatter to ORIGINAL rows via perm
    #pragma unroll
    for (int rr = 0; rr < 2; rr++) {
        int srow = wr + g + rr*8;
        int orow = g_perm[b * TT + srow];
        float* d = g_Y + ((size_t)(b * TT + orow)) * D_ + h * HD;
        #pragma unroll
        for (int nb2 = 0; nb2 < 8; nb2++) {
            int c = nb2*8 + 2*th;
            *(uint2*)&d[c] = make_uint2(f2tf32(oacc[nb2][rr*2+0] * inv[rr]),
                                        f2tf32(oacc[nb2][rr*2+1] * inv[rr]));
        }
    }
}

// ============================================================================
// Proj GEMM (unchanged): A = g_Y natural, B = W_proj^T LDS.64.
// ============================================================================
__global__ __launch_bounds__(256, 2) void proj_mma(
    const float* __restrict__ bias, float* __restrict__ out)
{
    extern __shared__ float smf[];
    const uint32_t sbU = smem_u32(smf);

    const int tid  = threadIdx.x;
    const int wid  = tid >> 5, lane = tid & 31;
    const int g = lane >> 2, th = lane & 3;
    const int wm = wid & 3, wn = wid >> 2;
    const int m0 = blockIdx.y * 128, n0 = blockIdx.x * 128;

    auto stage = [&](int k0, int buf) {
        const uint32_t adst = sbU + (buf ? (uint32_t)(SLABF*4) : 0u);
        const uint32_t bdst = adst + TILEF*4;
        #pragma unroll
        for (int i = 0; i < 4; i++) {
            int cid = tid + i * 256;
            int r = cid >> 3, c = cid & 7;
            cp16(adst + (r*LDA + c*4)*4, g_Y + (size_t)(m0 + r)*512 + k0 + c*4);
        }
        #pragma unroll
        for (int i = 0; i < 4; i++) {
            int cid = tid + i * 256;
            int r = cid >> 3, c = cid & 7;
            cp16(bdst + (r*LDA + c*4)*4, g_WpT + (size_t)(n0 + r)*512 + k0 + c*4);
        }
        CP_COMMIT();
    };

    float acc[2][8][4];
    #pragma unroll
    for (int mt = 0; mt < 2; mt++)
        #pragma unroll
        for (int nt = 0; nt < 8; nt++)
            #pragma unroll
            for (int j = 0; j < 4; j++) acc[mt][nt][j] = 0.f;

    stage(0, 0);
    #pragma unroll 1
    for (int it = 0; it < 16; it++) {
        const int buf = it & 1;
        if (it < 15) { stage((it + 1) * 32, buf ^ 1); CP_WAIT(1); }
        else         { CP_WAIT(0); }
        __syncthreads();

        const float* As = smf + (buf ? SLABF : 0);
        const float* Bs = As + TILEF;

        #pragma unroll
        for (int s = 0; s < 4; s++) {
            uint32_t aF[2][4];
            #pragma unroll
            for (int mt = 0; mt < 2; mt++) {
                int rb = wm * 32 + mt * 16 + g;
                aF[mt][0] = __float_as_uint(As[rb * LDA + s*8 + th]);
                aF[mt][1] = __float_as_uint(As[(rb + 8) * LDA + s*8 + th]);
                aF[mt][2] = __float_as_uint(As[rb * LDA + s*8 + th + 4]);
                aF[mt][3] = __float_as_uint(As[(rb + 8) * LDA + s*8 + th + 4]);
            }
            #pragma unroll
            for (int nt = 0; nt < 8; nt++) {
                int nc = wn * 64 + nt * 8 + g;
                uint2 bb = *(const uint2*)&Bs[nc * LDA + s*8 + 2*th];
                mma16n8k8(acc[0][nt], aF[0], bb.x, bb.y);
                mma16n8k8(acc[1][nt], aF[1], bb.x, bb.y);
            }
        }
        __syncthreads();
    }

    #pragma unroll
    for (int mt = 0; mt < 2; mt++) {
        #pragma unroll
        for (int r2 = 0; r2 < 2; r2++) {
            int row = m0 + wm * 32 + mt * 16 + g + r2 * 8;
            int bb = row >> 11;
            int tt = row & 2047;
            size_t base = (tt < T_)
                ? ((size_t)(bb * T_ + tt) * D_)
                : ((size_t)B_ * T_ * D_ + (size_t)(bb * T_ + (tt - T_)) * D_);
            #pragma unroll
            for (int nt = 0; nt < 8; nt++) {
                int col = n0 + wn * 64 + nt * 8 + 2 * th;
                float2 v = make_float2(acc[mt][nt][r2*2+0] + bias[col],
                                       acc[mt][nt][r2*2+1] + bias[col+1]);
                *(float2*)&out[base + col] = v;
            }
        }
    }
}

// ---------------------------------------------------------------------------
extern "C" void kernel_launch(void* const* d_in, const int* in_sizes, int n_in,
                              void* d_out, int out_size)
{
    const float* self_seq  = (const float*)d_in[0];
    const float* cross_seq = (const float*)d_in[1];
    const int*   t_self    = (const int*)d_in[2];
    const int*   t_cross   = (const int*)d_in[3];
    const float* W_self    = (const float*)d_in[4];
    const float* b_self    = (const float*)d_in[5];
    const float* W_cross   = (const float*)d_in[6];
    const float* b_cross   = (const float*)d_in[7];
    const float* W_proj    = (const float*)d_in[8];
    const float* b_proj    = (const float*)d_in[9];
    float* out = (float*)d_out;

    cudaFuncSetAttribute(attn_mma,
                         cudaFuncAttributeMaxDynamicSharedMemorySize, ATTN_SMEM);
    cudaFuncSetAttribute(qkv_mma,
                         cudaFuncAttributeMaxDynamicSharedMemorySize, GEMM_SMEM);
    cudaFuncSetAttribute(proj_mma,
                         cudaFuncAttributeMaxDynamicSharedMemorySize, GEMM_SMEM);

    sort_time<<<B_, 256>>>(t_self, t_cross);
    round_x<<<(2*NX8 + 255)/256, 256>>>(self_seq, cross_seq);
    wt_kernel<<<dim3(16, 48, 3), 256>>>(W_self, W_cross, W_proj);

    qkv_mma<<<dim3(12, 32, 2), 256, GEMM_SMEM>>>(b_self, b_cross);

    attn_mma<<<512, 256, ATTN_SMEM>>>();

    proj_mma<<<dim3(4, 64), 256, GEMM_SMEM>>>(b_proj, out);
}

// round 15
// speedup vs baseline: 1.3455x; 1.3455x over previous
#include <cuda_runtime.h>
#include <cstdint>

#define B_  4
#define T_  1024
#define TT  2048
#define D_  512
#define H_  8
#define HD  64

// Scratch (allocation-free rule: __device__ globals).
__device__ float g_Q[B_*H_*TT*HD];     // tf32 (b,h,pos,hd), pos = time-sorted
__device__ float g_K[B_*H_*TT*HD];     // tf32 (b,h,pos,hd), hd ilv8, sorted
__device__ float g_Vt[B_*H_*HD*TT];    // tf32 V^T (b,h,hd,pos), pos ilv8, sorted
__device__ float g_Y[B_*TT*D_];        // attn out, tf32, (b,t,d) ORIGINAL order
__device__ float g_rXs[B_*T_*D_];      // tf32, k ilv8
__device__ float g_rXc[B_*T_*D_];
__device__ float g_WsT[3*D_*D_];       // W^T (n,k), tf32, k ilv8
__device__ float g_WcT[3*D_*D_];
__device__ float g_WpT[D_*D_];
// time-sort outputs
__device__ int g_sortT[B_*TT];         // sorted times, ascending
__device__ int g_perm[B_*TT];          // sorted pos -> original index
__device__ int g_rank[B_*TT];          // original index -> sorted pos

__device__ __forceinline__ uint32_t f2tf32(float x) {
    uint32_t r;
    asm("cvt.rna.tf32.f32 %0, %1;" : "=r"(r) : "f"(x));
    return r;
}
__device__ __forceinline__ float fexp2(float x) {
    float y;
    asm("ex2.approx.f32 %0, %1;" : "=f"(y) : "f"(x));
    return y;
}
__device__ __forceinline__ int ilv8(int k) {
    return (k & ~7) | ((k & 3) << 1) | ((k & 4) >> 2);
}
__device__ __forceinline__ void mma16n8k8(float* c, const uint32_t* a,
                                          uint32_t b0, uint32_t b1) {
    asm volatile(
        "mma.sync.aligned.m16n8k8.row.col.f32.tf32.tf32.f32 "
        "{%0,%1,%2,%3}, {%4,%5,%6,%7}, {%8,%9}, {%0,%1,%2,%3};"
        : "+f"(c[0]), "+f"(c[1]), "+f"(c[2]), "+f"(c[3])
        : "r"(a[0]), "r"(a[1]), "r"(a[2]), "r"(a[3]), "r"(b0), "r"(b1));
}
__device__ __forceinline__ void cp16(uint32_t dst, const void* src) {
    asm volatile("cp.async.cg.shared.global [%0], [%1], 16;"
                 :: "r"(dst), "l"(src) : "memory");
}
#define CP_COMMIT() asm volatile("cp.async.commit_group;" ::: "memory")
#define CP_WAIT(n)  asm volatile("cp.async.wait_group %0;" :: "n"(n) : "memory")
__device__ __forceinline__ uint32_t smem_u32(const void* p) {
    uint32_t a;
    asm("{ .reg .u64 t; cvta.to.shared.u64 t, %1; cvt.u32.u64 %0, t; }"
        : "=r"(a) : "l"(p));
    return a;
}

// ============================================================================
// Fused pre-pass (single launch; each block takes exactly one branch):
//   blocks [0,4):          per-batch bitonic time sort -> sortT/perm/rank
//   blocks [4,2052):       round X to tf32 + k-interleave
//   blocks [2052,4356):    W transpose (k,n)->(n,k) + tf32 + k-interleave
// ============================================================================
#define NX8 (B_*T_*D_/8)
#define PB_SORT 4
#define PB_RX   2048
#define PB_WT   2304
#define PB_TOT  (PB_SORT + PB_RX + PB_WT)

__global__ __launch_bounds__(256) void prepass(
    const int* __restrict__ t_self, const int* __restrict__ t_cross,
    const float* __restrict__ Xs, const float* __restrict__ Xc,
    const float* __restrict__ Ws, const float* __restrict__ Wc,
    const float* __restrict__ Wp)
{
    __shared__ int st[2048];
    __shared__ int sp[2048];
    const int bx  = blockIdx.x;
    const int tid = threadIdx.x;

    if (bx < PB_SORT) {
        // ---- time sort (batch = bx) ----
        const int b = bx;
        for (int i = tid; i < 2048; i += 256) {
            st[i] = (i < T_) ? t_self[b*T_ + i] : t_cross[b*T_ + i - T_];
            sp[i] = i;
        }
        __syncthreads();
        for (int k = 2; k <= 2048; k <<= 1) {
            for (int j = k >> 1; j > 0; j >>= 1) {
                for (int i = tid; i < 2048; i += 256) {
                    int ixj = i ^ j;
                    if (ixj > i) {
                        bool up = ((i & k) == 0);
                        int t1 = st[i], t2 = st[ixj];
                        int p1 = sp[i], p2 = sp[ixj];
                        bool gt = (t1 > t2) || (t1 == t2 && p1 > p2);
                        if (gt == up) {
                            st[i] = t2; st[ixj] = t1;
                            sp[i] = p2; sp[ixj] = p1;
                        }
                    }
                }
                __syncthreads();
            }
        }
        for (int i = tid; i < 2048; i += 256) {
            g_sortT[b*TT + i] = st[i];
            g_perm[b*TT + i]  = sp[i];
            g_rank[b*TT + sp[i]] = i;
        }
    } else if (bx < PB_SORT + PB_RX) {
        // ---- round X (tf32 + k ilv8) ----
        int i = (bx - PB_SORT) * 256 + tid;
        if (i >= 2 * NX8) return;
        const float4* src = (i < NX8) ? (const float4*)Xs : (const float4*)Xc;
        float4* dst       = (i < NX8) ? (float4*)g_rXs    : (float4*)g_rXc;
        int j = (i < NX8) ? i : i - NX8;
        float4 a = src[2*j], b = src[2*j + 1];
        uint4 o0 = make_uint4(f2tf32(a.x), f2tf32(b.x), f2tf32(a.y), f2tf32(b.y));
        uint4 o1 = make_uint4(f2tf32(a.z), f2tf32(b.z), f2tf32(a.w), f2tf32(b.w));
        ((uint4*)dst)[2*j]     = o0;
        ((uint4*)dst)[2*j + 1] = o1;
    } else {
        // ---- W transpose (32x32 tile; reuse st[] as the staging buffer) ----
        int flat = bx - PB_SORT - PB_RX;      // 0..2303
        const int z  = flat / 768;
        const int r6 = flat % 768;
        const int kb = (r6 & 15) * 32;        // 16 kb tiles
        const int nby = r6 >> 4;              // 0..47
        if (z == 2 && nby >= 16) return;
        const int nb = nby * 32;
        const float* W = (z == 0) ? Ws : (z == 1) ? Wc : Wp;
        float* WT      = (z == 0) ? g_WsT : (z == 1) ? g_WcT : g_WpT;
        const int N = (z == 2) ? 512 : 1536;

        float* smw = (float*)st;              // 32x33 floats = 4224 B, fits
        #pragma unroll
        for (int i = tid; i < 1024; i += 256) {
            int r = i >> 5, c = i & 31;
            smw[r * 33 + c] = W[(size_t)(kb + r) * N + nb + c];
        }
        __syncthreads();
        #pragma unroll
        for (int i = tid; i < 1024; i += 256) {
            int nl = i >> 5, kp = i & 31;
            int klog = (kp & ~7) | ((kp & 1) << 2) | ((kp >> 1) & 3);
            WT[(size_t)(nb + nl) * 512 + kb + kp] =
                __uint_as_float(f2tf32(smw[klog * 33 + nl]));
        }
    }
}

// ============================================================================
// QKV GEMM: epilogue scatters Q/K/V to time-sorted positions via g_rank.
// ============================================================================
#define LDA 40
#define TILEF (128*LDA)
#define SLABF (2*TILEF)
#define GEMM_SMEM (2*SLABF*4)

__global__ __launch_bounds__(256, 2) void qkv_mma(
    const float* __restrict__ bS, const float* __restrict__ bC)
{
    extern __shared__ float smf[];
    const uint32_t sbU = smem_u32(smf);

    const int z = blockIdx.z;
    const float* X    = z ? g_rXc : g_rXs;
    const float* WT   = z ? g_WcT : g_WsT;
    const float* bias = z ? bC : bS;
    const int seq_off = z ? 1024 : 0;

    const int tid  = threadIdx.x;
    const int wid  = tid >> 5, lane = tid & 31;
    const int g = lane >> 2, th = lane & 3;
    const int wm = wid & 3, wn = wid >> 2;
    const int m0 = blockIdx.y * 128, n0 = blockIdx.x * 128;

    auto stage = [&](int k0, int buf) {
        const uint32_t adst = sbU + (buf ? (uint32_t)(SLABF*4) : 0u);
        const uint32_t bdst = adst + TILEF*4;
        #pragma unroll
        for (int i = 0; i < 4; i++) {
            int cid = tid + i * 256;
            int r = cid >> 3, c = cid & 7;
            cp16(adst + (r*LDA + c*4)*4, X + (size_t)(m0 + r)*512 + k0 + c*4);
        }
        #pragma unroll
        for (int i = 0; i < 4; i++) {
            int cid = tid + i * 256;
            int r = cid >> 3, c = cid & 7;
            cp16(bdst + (r*LDA + c*4)*4, WT + (size_t)(n0 + r)*512 + k0 + c*4);
        }
        CP_COMMIT();
    };

    float acc[2][8][4];
    #pragma unroll
    for (int mt = 0; mt < 2; mt++)
        #pragma unroll
        for (int nt = 0; nt < 8; nt++)
            #pragma unroll
            for (int j = 0; j < 4; j++) acc[mt][nt][j] = 0.f;

    stage(0, 0);
    #pragma unroll 1
    for (int it = 0; it < 16; it++) {
        const int buf = it & 1;
        if (it < 15) { stage((it + 1) * 32, buf ^ 1); CP_WAIT(1); }
        else         { CP_WAIT(0); }
        __syncthreads();

        const float* As = smf + (buf ? SLABF : 0);
        const float* Bs = As + TILEF;

        #pragma unroll
        for (int s = 0; s < 4; s++) {
            uint32_t aF[2][4];
            #pragma unroll
            for (int mt = 0; mt < 2; mt++) {
                int rb = wm * 32 + mt * 16 + g;
                uint2 aLo = *(const uint2*)&As[rb * LDA + s*8 + 2*th];
                uint2 aHi = *(const uint2*)&As[(rb + 8) * LDA + s*8 + 2*th];
                aF[mt][0] = aLo.x; aF[mt][1] = aHi.x;
                aF[mt][2] = aLo.y; aF[mt][3] = aHi.y;
            }
            #pragma unroll
            for (int nt = 0; nt < 8; nt++) {
                int nc = wn * 64 + nt * 8 + g;
                uint2 bb = *(const uint2*)&Bs[nc * LDA + s*8 + 2*th];
                mma16n8k8(acc[0][nt], aF[0], bb.x, bb.y);
                mma16n8k8(acc[1][nt], aF[1], bb.x, bb.y);
            }
        }
        __syncthreads();
    }

    #pragma unroll
    for (int mt = 0; mt < 2; mt++) {
        #pragma unroll
        for (int r2 = 0; r2 < 2; r2++) {
            int row = m0 + wm * 32 + mt * 16 + g + r2 * 8;
            int bb = row >> 10;
            int tg = (row & 1023) + seq_off;
            int pos = g_rank[bb * TT + tg];          // time-sorted position
            #pragma unroll
            for (int nt = 0; nt < 8; nt++) {
                int col = n0 + wn * 64 + nt * 8 + 2 * th;
                float v0 = acc[mt][nt][r2*2+0] + bias[col];
                float v1 = acc[mt][nt][r2*2+1] + bias[col+1];
                int sel = col >> 9, c = col & 511;
                int h = c >> 6, dd = c & 63;
                if (sel == 2) {
                    int tgp = (pos & ~7) | ((pos & 3) << 1) | ((pos & 4) >> 2);
                    float* dv = g_Vt + ((((size_t)bb * H_ + h) * HD + dd) * TT) + tgp;
                    dv[0]  = __uint_as_float(f2tf32(v0));
                    dv[TT] = __uint_as_float(f2tf32(v1));
                } else if (sel == 1) {
                    size_t base = (((size_t)bb * H_ + h) * TT + pos) << 6;
                    g_K[base + ilv8(dd)]     = __uint_as_float(f2tf32(v0));
                    g_K[base + ilv8(dd + 1)] = __uint_as_float(f2tf32(v1));
                } else {
                    size_t off = ((((size_t)bb * H_ + h) * TT + pos) << 6) + dd;
                    g_Q[off]     = __uint_as_float(f2tf32(v0));
                    g_Q[off + 1] = __uint_as_float(f2tf32(v1));
                }
            }
        }
    }
}

// ============================================================================
// Flash attention on time-sorted tokens, k-loop bounded by nkt.
// R13 grid/order restored: dim3(16,32), per-bh heavy-first (consecutive CTAs
// share one bh's K/V through L2 — measured best). ~47% of tiles skipped.
// ============================================================================
#define KT  64
#define NKT 32
#define LDK 72
#define LDV 72
#define LDP 68
#define K0B 0
#define K1B 18432
#define V0B 36864
#define V1B 55296
#define PB  73728
#define T0B 108544
#define T1B 108800
#define ATTN_SMEM 109056

__global__ __launch_bounds__(256, 2) void attn_mma(void)
{
    extern __shared__ char smc[];
    const uint32_t sbU = smem_u32(smc);

    const int tid  = threadIdx.x;
    const int wid  = tid >> 5;
    const int lane = tid & 31;
    const int g    = lane >> 2;
    const int th   = lane & 3;
    const int bh   = blockIdx.y, b = bh >> 3, h = bh & 7;
    const int qt   = (int)(gridDim.x - 1) - (int)blockIdx.x;  // heavy tiles first per bh
    const int q0   = qt * 128;

    const float* Qg = g_Q + (size_t)bh * TT * HD;
    const float* Kg = g_K + (size_t)bh * TT * HD;
    const float* Vg = g_Vt + (size_t)bh * HD * TT;
    const int* sT   = g_sortT + b * TT;

    const int maxtq = sT[q0 + 127];
    int nkt;
    {
        bool pred = (sT[lane << 6] <= maxtq);
        nkt = __popc(__ballot_sync(0xffffffffu, pred));
    }

    auto issue = [&](int kt, int bufsel) {
        const int k0 = kt * KT;
        const uint32_t kdst = sbU + (bufsel ? K1B : K0B);
        const uint32_t vdst = sbU + (bufsel ? V1B : V0B);
        #pragma unroll
        for (int i = 0; i < 4; i++) {
            int idx = tid + i * 256;
            int row = idx >> 4, c = idx & 15;
            cp16(kdst + row * (LDK*4) + c * 16,
                 Kg + (size_t)(k0 + row) * HD + c * 4);
        }
        #pragma unroll
        for (int i = 0; i < 4; i++) {
            int idx = tid + i * 256;
            int row = idx >> 4, c = idx & 15;
            cp16(vdst + row * (LDV*4) + c * 16,
                 Vg + (size_t)row * TT + k0 + c * 4);
        }
        if (tid < 16) {
            cp16(sbU + (bufsel ? T1B : T0B) + tid * 16, sT + k0 + tid * 4);
        }
        CP_COMMIT();
    };
    issue(0, 0);

    const int wr = q0 + wid * 16;

    uint32_t aQ[8][4];
    {
        const float* qp0 = Qg + (size_t)(wr + g) * HD;
        const float* qp1 = Qg + (size_t)(wr + g + 8) * HD;
        #pragma unroll
        for (int s = 0; s < 8; s++) {
            aQ[s][0] = __float_as_uint(qp0[s*8 + th]);
            aQ[s][1] = __float_as_uint(qp1[s*8 + th]);
            aQ[s][2] = __float_as_uint(qp0[s*8 + th + 4]);
            aQ[s][3] = __float_as_uint(qp1[s*8 + th + 4]);
        }
    }
    int tq[2];
    #pragma unroll
    for (int rr = 0; rr < 2; rr++)
        tq[rr] = sT[wr + g + rr*8];

    float oacc[8][4];
    #pragma unroll
    for (int n = 0; n < 8; n++)
        #pragma unroll
        for (int j = 0; j < 4; j++) oacc[n][j] = 0.f;
    float l0 = 0.f, l1 = 0.f;

    float* Pw = (float*)(smc + PB) + wid * 16 * LDP;
    const float E = 0.125f * 1.44269504f;

    #pragma unroll 1
    for (int kt = 0; kt < nkt; kt++) {
        const int buf = kt & 1;
        if (kt < nkt - 1) { issue(kt + 1, buf ^ 1); CP_WAIT(1); }
        else              { CP_WAIT(0); }
        __syncthreads();

        const float* Ks  = (const float*)(smc + (buf ? K1B : K0B));
        const float* Vs  = (const float*)(smc + (buf ? V1B : V0B));
        const int*   tks = (const int*)(smc + (buf ? T1B : T0B));

        // ---- S = Q K^T in nb-PAIRS (two independent MMA chains) ----
        #pragma unroll
        for (int nb = 0; nb < 8; nb += 2) {
            float sa0[4] = {0.f, 0.f, 0.f, 0.f};
            float sa1[4] = {0.f, 0.f, 0.f, 0.f};
            const float* kr0 = &Ks[(nb*8 + g) * LDK];
            const float* kr1 = &Ks[((nb+1)*8 + g) * LDK];
            #pragma unroll
            for (int s = 0; s < 8; s++) {
                uint2 k0v = *(const uint2*)&kr0[s*8 + 2*th];
                uint2 k1v = *(const uint2*)&kr1[s*8 + 2*th];
                mma16n8k8(sa0, aQ[s], k0v.x, k0v.y);
                mma16n8k8(sa1, aQ[s], k1v.x, k1v.y);
            }
            #pragma unroll
            for (int u = 0; u < 2; u++) {
                const float* sa = u ? sa1 : sa0;
                const int c0 = (nb + u)*8 + 2*th;
                const int tk0 = tks[c0], tk1 = tks[c0 + 1];
                float p00 = (tq[0] >= tk0) ? fexp2(sa[0] * E) : 0.f;
                float p01 = (tq[0] >= tk1) ? fexp2(sa[1] * E) : 0.f;
                float p10 = (tq[1] >= tk0) ? fexp2(sa[2] * E) : 0.f;
                float p11 = (tq[1] >= tk1) ? fexp2(sa[3] * E) : 0.f;
                l0 += p00 + p01;  l1 += p10 + p11;
                *(uint2*)&Pw[g * LDP + c0] =
                    make_uint2(f2tf32(p00), f2tf32(p01));
                *(uint2*)&Pw[(g + 8) * LDP + c0] =
                    make_uint2(f2tf32(p10), f2tf32(p11));
            }
        }
        __syncwarp();   // P is per-warp private

        // ---- O += P V ----
        #pragma unroll
        for (int s2 = 0; s2 < 8; s2++) {
            uint32_t aP[4];
            aP[0] = __float_as_uint(Pw[g * LDP + s2*8 + th]);
            aP[1] = __float_as_uint(Pw[(g + 8) * LDP + s2*8 + th]);
            aP[2] = __float_as_uint(Pw[g * LDP + s2*8 + th + 4]);
            aP[3] = __float_as_uint(Pw[(g + 8) * LDP + s2*8 + th + 4]);
            #pragma unroll
            for (int nb2 = 0; nb2 < 8; nb2++) {
                const float* vrow = &Vs[(nb2*8 + g) * LDV];
                uint2 vb = *(const uint2*)&vrow[s2*8 + 2*th];
                mma16n8k8(oacc[nb2], aP, vb.x, vb.y);
            }
        }
        __syncthreads();   // all reads of buf done before refill
    }

    l0 += __shfl_xor_sync(0xffffffffu, l0, 1);
    l0 += __shfl_xor_sync(0xffffffffu, l0, 2);
    l1 += __shfl_xor_sync(0xffffffffu, l1, 1);
    l1 += __shfl_xor_sync(0xffffffffu, l1, 2);
    float inv[2] = {1.f / l0, 1.f / l1};

    // scatter to ORIGINAL rows via perm
    #pragma unroll
    for (int rr = 0; rr < 2; rr++) {
        int srow = wr + g + rr*8;
        int orow = g_perm[b * TT + srow];
        float* d = g_Y + ((size_t)(b * TT + orow)) * D_ + h * HD;
        #pragma unroll
        for (int nb2 = 0; nb2 < 8; nb2++) {
            int c = nb2*8 + 2*th;
            *(uint2*)&d[c] = make_uint2(f2tf32(oacc[nb2][rr*2+0] * inv[rr]),
                                        f2tf32(oacc[nb2][rr*2+1] * inv[rr]));
        }
    }
}

// ============================================================================
// Proj GEMM (unchanged): A = g_Y natural, B = W_proj^T LDS.64.
// ============================================================================
__global__ __launch_bounds__(256, 2) void proj_mma(
    const float* __restrict__ bias, float* __restrict__ out)
{
    extern __shared__ float smf[];
    const uint32_t sbU = smem_u32(smf);

    const int tid  = threadIdx.x;
    const int wid  = tid >> 5, lane = tid & 31;
    const int g = lane >> 2, th = lane & 3;
    const int wm = wid & 3, wn = wid >> 2;
    const int m0 = blockIdx.y * 128, n0 = blockIdx.x * 128;

    auto stage = [&](int k0, int buf) {
        const uint32_t adst = sbU + (buf ? (uint32_t)(SLABF*4) : 0u);
        const uint32_t bdst = adst + TILEF*4;
        #pragma unroll
        for (int i = 0; i < 4; i++) {
            int cid = tid + i * 256;
            int r = cid >> 3, c = cid & 7;
            cp16(adst + (r*LDA + c*4)*4, g_Y + (size_t)(m0 + r)*512 + k0 + c*4);
        }
        #pragma unroll
        for (int i = 0; i < 4; i++) {
            int cid = tid + i * 256;
            int r = cid >> 3, c = cid & 7;
            cp16(bdst + (r*LDA + c*4)*4, g_WpT + (size_t)(n0 + r)*512 + k0 + c*4);
        }
        CP_COMMIT();
    };

    float acc[2][8][4];
    #pragma unroll
    for (int mt = 0; mt < 2; mt++)
        #pragma unroll
        for (int nt = 0; nt < 8; nt++)
            #pragma unroll
            for (int j = 0; j < 4; j++) acc[mt][nt][j] = 0.f;

    stage(0, 0);
    #pragma unroll 1
    for (int it = 0; it < 16; it++) {
        const int buf = it & 1;
        if (it < 15) { stage((it + 1) * 32, buf ^ 1); CP_WAIT(1); }
        else         { CP_WAIT(0); }
        __syncthreads();

        const float* As = smf + (buf ? SLABF : 0);
        const float* Bs = As + TILEF;

        #pragma unroll
        for (int s = 0; s < 4; s++) {
            uint32_t aF[2][4];
            #pragma unroll
            for (int mt = 0; mt < 2; mt++) {
                int rb = wm * 32 + mt * 16 + g;
                aF[mt][0] = __float_as_uint(As[rb * LDA + s*8 + th]);
                aF[mt][1] = __float_as_uint(As[(rb + 8) * LDA + s*8 + th]);
                aF[mt][2] = __float_as_uint(As[rb * LDA + s*8 + th + 4]);
                aF[mt][3] = __float_as_uint(As[(rb + 8) * LDA + s*8 + th + 4]);
            }
            #pragma unroll
            for (int nt = 0; nt < 8; nt++) {
                int nc = wn * 64 + nt * 8 + g;
                uint2 bb = *(const uint2*)&Bs[nc * LDA + s*8 + 2*th];
                mma16n8k8(acc[0][nt], aF[0], bb.x, bb.y);
                mma16n8k8(acc[1][nt], aF[1], bb.x, bb.y);
            }
        }
        __syncthreads();
    }

    #pragma unroll
    for (int mt = 0; mt < 2; mt++) {
        #pragma unroll
        for (int r2 = 0; r2 < 2; r2++) {
            int row = m0 + wm * 32 + mt * 16 + g + r2 * 8;
            int bb = row >> 11;
            int tt = row & 2047;
            size_t base = (tt < T_)
                ? ((size_t)(bb * T_ + tt) * D_)
                : ((size_t)B_ * T_ * D_ + (size_t)(bb * T_ + (tt - T_)) * D_);
            #pragma unroll
            for (int nt = 0; nt < 8; nt++) {
                int col = n0 + wn * 64 + nt * 8 + 2 * th;
                float2 v = make_float2(acc[mt][nt][r2*2+0] + bias[col],
                                       acc[mt][nt][r2*2+1] + bias[col+1]);
                *(float2*)&out[base + col] = v;
            }
        }
    }
}

// ---------------------------------------------------------------------------
extern "C" void kernel_launch(void* const* d_in, const int* in_sizes, int n_in,
                              void* d_out, int out_size)
{
    const float* self_seq  = (const float*)d_in[0];
    const float* cross_seq = (const float*)d_in[1];
    const int*   t_self    = (const int*)d_in[2];
    const int*   t_cross   = (const int*)d_in[3];
    const float* W_self    = (const float*)d_in[4];
    const float* b_self    = (const float*)d_in[5];
    const float* W_cross   = (const float*)d_in[6];
    const float* b_cross   = (const float*)d_in[7];
    const float* W_proj    = (const float*)d_in[8];
    const float* b_proj    = (const float*)d_in[9];
    float* out = (float*)d_out;

    cudaFuncSetAttribute(attn_mma,
                         cudaFuncAttributeMaxDynamicSharedMemorySize, ATTN_SMEM);
    cudaFuncSetAttribute(qkv_mma,
                         cudaFuncAttributeMaxDynamicSharedMemorySize, GEMM_SMEM);
    cudaFuncSetAttribute(proj_mma,
                         cudaFuncAttributeMaxDynamicSharedMemorySize, GEMM_SMEM);

    prepass<<<PB_TOT, 256>>>(t_self, t_cross, self_seq, cross_seq,
                             W_self, W_cross, W_proj);

    qkv_mma<<<dim3(12, 32, 2), 256, GEMM_SMEM>>>(b_self, b_cross);

    attn_mma<<<dim3(16, 32), 256, ATTN_SMEM>>>();

    proj_mma<<<dim3(4, 64), 256, GEMM_SMEM>>>(b_proj, out);
}

// round 16
// speedup vs baseline: 1.3743x; 1.0214x over previous
#include <cuda_runtime.h>
#include <cstdint>

#define B_  4
#define T_  1024
#define TT  2048
#define D_  512
#define H_  8
#define HD  64

// Scratch (allocation-free rule: __device__ globals).
__device__ float g_Q[B_*H_*TT*HD];     // tf32 (b,h,pos,hd), pos = time-sorted
__device__ float g_K[B_*H_*TT*HD];     // tf32 (b,h,pos,hd), hd ilv8, sorted
__device__ float g_Vt[B_*H_*HD*TT];    // tf32 V^T (b,h,hd,pos), pos ilv8, sorted
__device__ float g_Y[B_*TT*D_];        // attn out, tf32, (b,t,d) ORIGINAL order
__device__ float g_rXs[B_*T_*D_];      // tf32, k ilv8
__device__ float g_rXc[B_*T_*D_];
__device__ float g_WsT[3*D_*D_];       // W^T (n,k), tf32, k ilv8
__device__ float g_WcT[3*D_*D_];
__device__ float g_WpT[D_*D_];
// time-sort outputs
__device__ int g_sortT[B_*TT];         // sorted times, ascending
__device__ int g_perm[B_*TT];          // sorted pos -> original index
__device__ int g_rank[B_*TT];          // original index -> sorted pos

__device__ __forceinline__ uint32_t f2tf32(float x) {
    uint32_t r;
    asm("cvt.rna.tf32.f32 %0, %1;" : "=r"(r) : "f"(x));
    return r;
}
__device__ __forceinline__ float fexp2(float x) {
    float y;
    asm("ex2.approx.f32 %0, %1;" : "=f"(y) : "f"(x));
    return y;
}
__device__ __forceinline__ int ilv8(int k) {
    return (k & ~7) | ((k & 3) << 1) | ((k & 4) >> 2);
}
__device__ __forceinline__ void mma16n8k8(float* c, const uint32_t* a,
                                          uint32_t b0, uint32_t b1) {
    asm volatile(
        "mma.sync.aligned.m16n8k8.row.col.f32.tf32.tf32.f32 "
        "{%0,%1,%2,%3}, {%4,%5,%6,%7}, {%8,%9}, {%0,%1,%2,%3};"
        : "+f"(c[0]), "+f"(c[1]), "+f"(c[2]), "+f"(c[3])
        : "r"(a[0]), "r"(a[1]), "r"(a[2]), "r"(a[3]), "r"(b0), "r"(b1));
}
__device__ __forceinline__ void cp16(uint32_t dst, const void* src) {
    asm volatile("cp.async.cg.shared.global [%0], [%1], 16;"
                 :: "r"(dst), "l"(src) : "memory");
}
#define CP_COMMIT() asm volatile("cp.async.commit_group;" ::: "memory")
#define CP_WAIT(n)  asm volatile("cp.async.wait_group %0;" :: "n"(n) : "memory")
__device__ __forceinline__ uint32_t smem_u32(const void* p) {
    uint32_t a;
    asm("{ .reg .u64 t; cvta.to.shared.u64 t, %1; cvt.u32.u64 %0, t; }"
        : "=r"(a) : "l"(p));
    return a;
}

// ============================================================================
// Fused pre-pass (single launch; each block takes exactly one branch).
// ============================================================================
#define NX8 (B_*T_*D_/8)
#define PB_SORT 4
#define PB_RX   2048
#define PB_WT   2304
#define PB_TOT  (PB_SORT + PB_RX + PB_WT)

__global__ __launch_bounds__(256) void prepass(
    const int* __restrict__ t_self, const int* __restrict__ t_cross,
    const float* __restrict__ Xs, const float* __restrict__ Xc,
    const float* __restrict__ Ws, const float* __restrict__ Wc,
    const float* __restrict__ Wp)
{
    __shared__ int st[2048];
    __shared__ int sp[2048];
    const int bx  = blockIdx.x;
    const int tid = threadIdx.x;

    if (bx < PB_SORT) {
        const int b = bx;
        for (int i = tid; i < 2048; i += 256) {
            st[i] = (i < T_) ? t_self[b*T_ + i] : t_cross[b*T_ + i - T_];
            sp[i] = i;
        }
        __syncthreads();
        for (int k = 2; k <= 2048; k <<= 1) {
            for (int j = k >> 1; j > 0; j >>= 1) {
                for (int i = tid; i < 2048; i += 256) {
                    int ixj = i ^ j;
                    if (ixj > i) {
                        bool up = ((i & k) == 0);
                        int t1 = st[i], t2 = st[ixj];
                        int p1 = sp[i], p2 = sp[ixj];
                        bool gt = (t1 > t2) || (t1 == t2 && p1 > p2);
                        if (gt == up) {
                            st[i] = t2; st[ixj] = t1;
                            sp[i] = p2; sp[ixj] = p1;
                        }
                    }
                }
                __syncthreads();
            }
        }
        for (int i = tid; i < 2048; i += 256) {
            g_sortT[b*TT + i] = st[i];
            g_perm[b*TT + i]  = sp[i];
            g_rank[b*TT + sp[i]] = i;
        }
    } else if (bx < PB_SORT + PB_RX) {
        int i = (bx - PB_SORT) * 256 + tid;
        if (i >= 2 * NX8) return;
        const float4* src = (i < NX8) ? (const float4*)Xs : (const float4*)Xc;
        float4* dst       = (i < NX8) ? (float4*)g_rXs    : (float4*)g_rXc;
        int j = (i < NX8) ? i : i - NX8;
        float4 a = src[2*j], b = src[2*j + 1];
        uint4 o0 = make_uint4(f2tf32(a.x), f2tf32(b.x), f2tf32(a.y), f2tf32(b.y));
        uint4 o1 = make_uint4(f2tf32(a.z), f2tf32(b.z), f2tf32(a.w), f2tf32(b.w));
        ((uint4*)dst)[2*j]     = o0;
        ((uint4*)dst)[2*j + 1] = o1;
    } else {
        int flat = bx - PB_SORT - PB_RX;
        const int z  = flat / 768;
        const int r6 = flat % 768;
        const int kb = (r6 & 15) * 32;
        const int nby = r6 >> 4;
        if (z == 2 && nby >= 16) return;
        const int nb = nby * 32;
        const float* W = (z == 0) ? Ws : (z == 1) ? Wc : Wp;
        float* WT      = (z == 0) ? g_WsT : (z == 1) ? g_WcT : g_WpT;
        const int N = (z == 2) ? 512 : 1536;

        float* smw = (float*)st;
        #pragma unroll
        for (int i = tid; i < 1024; i += 256) {
            int r = i >> 5, c = i & 31;
            smw[r * 33 + c] = W[(size_t)(kb + r) * N + nb + c];
        }
        __syncthreads();
        #pragma unroll
        for (int i = tid; i < 1024; i += 256) {
            int nl = i >> 5, kp = i & 31;
            int klog = (kp & ~7) | ((kp & 1) << 2) | ((kp >> 1) & 3);
            WT[(size_t)(nb + nl) * 512 + kb + kp] =
                __uint_as_float(f2tf32(smw[klog * 33 + nl]));
        }
    }
}

// ============================================================================
// QKV GEMM, PERSISTENT: 296 CTAs loop over all 768 tiles (kills the 0.6-wave
// tail of the 768-CTA grid). Epilogue scatters via g_rank. Frags LDS.64.
// ============================================================================
#define LDA 40
#define TILEF (128*LDA)
#define SLABF (2*TILEF)
#define GEMM_SMEM (2*SLABF*4)
#define QKV_CTAS 296
#define QKV_TILES 768

__global__ __launch_bounds__(256, 2) void qkv_mma(
    const float* __restrict__ bS, const float* __restrict__ bC)
{
    extern __shared__ float smf[];
    const uint32_t sbU = smem_u32(smf);

    const int tid  = threadIdx.x;
    const int wid  = tid >> 5, lane = tid & 31;
    const int g = lane >> 2, th = lane & 3;
    const int wm = wid & 3, wn = wid >> 2;

    for (int tile = blockIdx.x; tile < QKV_TILES; tile += QKV_CTAS) {
        const int z  = tile >= 384;
        const int r  = tile - (z ? 384 : 0);
        const int m0 = (r / 12) * 128;
        const int n0 = (r % 12) * 128;
        const float* X    = z ? g_rXc : g_rXs;
        const float* WT   = z ? g_WcT : g_WsT;
        const float* bias = z ? bC : bS;
        const int seq_off = z ? 1024 : 0;

        auto stage = [&](int k0, int buf) {
            const uint32_t adst = sbU + (buf ? (uint32_t)(SLABF*4) : 0u);
            const uint32_t bdst = adst + TILEF*4;
            #pragma unroll
            for (int i = 0; i < 4; i++) {
                int cid = tid + i * 256;
                int rr = cid >> 3, c = cid & 7;
                cp16(adst + (rr*LDA + c*4)*4, X + (size_t)(m0 + rr)*512 + k0 + c*4);
            }
            #pragma unroll
            for (int i = 0; i < 4; i++) {
                int cid = tid + i * 256;
                int rr = cid >> 3, c = cid & 7;
                cp16(bdst + (rr*LDA + c*4)*4, WT + (size_t)(n0 + rr)*512 + k0 + c*4);
            }
            CP_COMMIT();
        };

        float acc[2][8][4];
        #pragma unroll
        for (int mt = 0; mt < 2; mt++)
            #pragma unroll
            for (int nt = 0; nt < 8; nt++)
                #pragma unroll
                for (int j = 0; j < 4; j++) acc[mt][nt][j] = 0.f;

        stage(0, 0);
        #pragma unroll 1
        for (int it = 0; it < 16; it++) {
            const int buf = it & 1;
            if (it < 15) { stage((it + 1) * 32, buf ^ 1); CP_WAIT(1); }
            else         { CP_WAIT(0); }
            __syncthreads();

            const float* As = smf + (buf ? SLABF : 0);
            const float* Bs = As + TILEF;

            #pragma unroll
            for (int s = 0; s < 4; s++) {
                uint32_t aF[2][4];
                #pragma unroll
                for (int mt = 0; mt < 2; mt++) {
                    int rb = wm * 32 + mt * 16 + g;
                    uint2 aLo = *(const uint2*)&As[rb * LDA + s*8 + 2*th];
                    uint2 aHi = *(const uint2*)&As[(rb + 8) * LDA + s*8 + 2*th];
                    aF[mt][0] = aLo.x; aF[mt][1] = aHi.x;
                    aF[mt][2] = aLo.y; aF[mt][3] = aHi.y;
                }
                #pragma unroll
                for (int nt = 0; nt < 8; nt++) {
                    int nc = wn * 64 + nt * 8 + g;
                    uint2 bb = *(const uint2*)&Bs[nc * LDA + s*8 + 2*th];
                    mma16n8k8(acc[0][nt], aF[0], bb.x, bb.y);
                    mma16n8k8(acc[1][nt], aF[1], bb.x, bb.y);
                }
            }
            __syncthreads();
        }

        #pragma unroll
        for (int mt = 0; mt < 2; mt++) {
            #pragma unroll
            for (int r2 = 0; r2 < 2; r2++) {
                int row = m0 + wm * 32 + mt * 16 + g + r2 * 8;
                int bb = row >> 10;
                int tg = (row & 1023) + seq_off;
                int pos = g_rank[bb * TT + tg];
                #pragma unroll
                for (int nt = 0; nt < 8; nt++) {
                    int col = n0 + wn * 64 + nt * 8 + 2 * th;
                    float v0 = acc[mt][nt][r2*2+0] + bias[col];
                    float v1 = acc[mt][nt][r2*2+1] + bias[col+1];
                    int sel = col >> 9, c = col & 511;
                    int h = c >> 6, dd = c & 63;
                    if (sel == 2) {
                        int tgp = (pos & ~7) | ((pos & 3) << 1) | ((pos & 4) >> 2);
                        float* dv = g_Vt + ((((size_t)bb * H_ + h) * HD + dd) * TT) + tgp;
                        dv[0]  = __uint_as_float(f2tf32(v0));
                        dv[TT] = __uint_as_float(f2tf32(v1));
                    } else if (sel == 1) {
                        size_t base = (((size_t)bb * H_ + h) * TT + pos) << 6;
                        g_K[base + ilv8(dd)]     = __uint_as_float(f2tf32(v0));
                        g_K[base + ilv8(dd + 1)] = __uint_as_float(f2tf32(v1));
                    } else {
                        size_t off = ((((size_t)bb * H_ + h) * TT + pos) << 6) + dd;
                        g_Q[off]     = __uint_as_float(f2tf32(v0));
                        g_Q[off + 1] = __uint_as_float(f2tf32(v1));
                    }
                }
            }
        }
        __syncthreads();   // buffers reused by next tile
    }
}

// ============================================================================
// Flash attention on time-sorted tokens (R13/R15 config) + fully-live fast
// path: sorted order means tile fully live for this warp iff
// sT[k0+63] <= sT[wr] — skip tks loads and mask SELs (mask provably true).
// ============================================================================
#define KT  64
#define NKT 32
#define LDK 72
#define LDV 72
#define LDP 68
#define K0B 0
#define K1B 18432
#define V0B 36864
#define V1B 55296
#define PB  73728
#define T0B 108544
#define T1B 108800
#define ATTN_SMEM 109056

__global__ __launch_bounds__(256, 2) void attn_mma(void)
{
    extern __shared__ char smc[];
    const uint32_t sbU = smem_u32(smc);

    const int tid  = threadIdx.x;
    const int wid  = tid >> 5;
    const int lane = tid & 31;
    const int g    = lane >> 2;
    const int th   = lane & 3;
    const int bh   = blockIdx.y, b = bh >> 3, h = bh & 7;
    const int qt   = (int)(gridDim.x - 1) - (int)blockIdx.x;  // heavy first per bh
    const int q0   = qt * 128;

    const float* Qg = g_Q + (size_t)bh * TT * HD;
    const float* Kg = g_K + (size_t)bh * TT * HD;
    const float* Vg = g_Vt + (size_t)bh * HD * TT;
    const int* sT   = g_sortT + b * TT;

    const int maxtq = sT[q0 + 127];
    int nkt;
    {
        bool pred = (sT[lane << 6] <= maxtq);
        nkt = __popc(__ballot_sync(0xffffffffu, pred));
    }

    auto issue = [&](int kt, int bufsel) {
        const int k0 = kt * KT;
        const uint32_t kdst = sbU + (bufsel ? K1B : K0B);
        const uint32_t vdst = sbU + (bufsel ? V1B : V0B);
        #pragma unroll
        for (int i = 0; i < 4; i++) {
            int idx = tid + i * 256;
            int row = idx >> 4, c = idx & 15;
            cp16(kdst + row * (LDK*4) + c * 16,
                 Kg + (size_t)(k0 + row) * HD + c * 4);
        }
        #pragma unroll
        for (int i = 0; i < 4; i++) {
            int idx = tid + i * 256;
            int row = idx >> 4, c = idx & 15;
            cp16(vdst + row * (LDV*4) + c * 16,
                 Vg + (size_t)row * TT + k0 + c * 4);
        }
        if (tid < 16) {
            cp16(sbU + (bufsel ? T1B : T0B) + tid * 16, sT + k0 + tid * 4);
        }
        CP_COMMIT();
    };
    issue(0, 0);

    const int wr = q0 + wid * 16;
    const int wmin = sT[wr];   // warp's min tq (rows sorted ascending)

    uint32_t aQ[8][4];
    {
        const float* qp0 = Qg + (size_t)(wr + g) * HD;
        const float* qp1 = Qg + (size_t)(wr + g + 8) * HD;
        #pragma unroll
        for (int s = 0; s < 8; s++) {
            aQ[s][0] = __float_as_uint(qp0[s*8 + th]);
            aQ[s][1] = __float_as_uint(qp1[s*8 + th]);
            aQ[s][2] = __float_as_uint(qp0[s*8 + th + 4]);
            aQ[s][3] = __float_as_uint(qp1[s*8 + th + 4]);
        }
    }
    int tq[2];
    #pragma unroll
    for (int rr = 0; rr < 2; rr++)
        tq[rr] = sT[wr + g + rr*8];

    float oacc[8][4];
    #pragma unroll
    for (int n = 0; n < 8; n++)
        #pragma unroll
        for (int j = 0; j < 4; j++) oacc[n][j] = 0.f;
    float l0 = 0.f, l1 = 0.f;

    float* Pw = (float*)(smc + PB) + wid * 16 * LDP;
    const float E = 0.125f * 1.44269504f;

    #pragma unroll 1
    for (int kt = 0; kt < nkt; kt++) {
        const int buf = kt & 1;
        if (kt < nkt - 1) { issue(kt + 1, buf ^ 1); CP_WAIT(1); }
        else              { CP_WAIT(0); }
        __syncthreads();

        const float* Ks  = (const float*)(smc + (buf ? K1B : K0B));
        const float* Vs  = (const float*)(smc + (buf ? V1B : V0B));
        const int*   tks = (const int*)(smc + (buf ? T1B : T0B));

        // fully live for every row of this warp? (both sides sorted)
        const bool fullLive = (tks[63] <= wmin);

        // ---- S = Q K^T in nb-PAIRS (two independent MMA chains) ----
        #pragma unroll
        for (int nb = 0; nb < 8; nb += 2) {
            float sa0[4] = {0.f, 0.f, 0.f, 0.f};
            float sa1[4] = {0.f, 0.f, 0.f, 0.f};
            const float* kr0 = &Ks[(nb*8 + g) * LDK];
            const float* kr1 = &Ks[((nb+1)*8 + g) * LDK];
            #pragma unroll
            for (int s = 0; s < 8; s++) {
                uint2 k0v = *(const uint2*)&kr0[s*8 + 2*th];
                uint2 k1v = *(const uint2*)&kr1[s*8 + 2*th];
                mma16n8k8(sa0, aQ[s], k0v.x, k0v.y);
                mma16n8k8(sa1, aQ[s], k1v.x, k1v.y);
            }
            #pragma unroll
            for (int u = 0; u < 2; u++) {
                const float* sa = u ? sa1 : sa0;
                const int c0 = (nb + u)*8 + 2*th;
                float p00, p01, p10, p11;
                if (fullLive) {
                    p00 = fexp2(sa[0] * E);
                    p01 = fexp2(sa[1] * E);
                    p10 = fexp2(sa[2] * E);
                    p11 = fexp2(sa[3] * E);
                } else {
                    const int tk0 = tks[c0], tk1 = tks[c0 + 1];
                    p00 = (tq[0] >= tk0) ? fexp2(sa[0] * E) : 0.f;
                    p01 = (tq[0] >= tk1) ? fexp2(sa[1] * E) : 0.f;
                    p10 = (tq[1] >= tk0) ? fexp2(sa[2] * E) : 0.f;
                    p11 = (tq[1] >= tk1) ? fexp2(sa[3] * E) : 0.f;
                }
                l0 += p00 + p01;  l1 += p10 + p11;
                *(uint2*)&Pw[g * LDP + c0] =
                    make_uint2(f2tf32(p00), f2tf32(p01));
                *(uint2*)&Pw[(g + 8) * LDP + c0] =
                    make_uint2(f2tf32(p10), f2tf32(p11));
            }
        }
        __syncwarp();   // P is per-warp private

        // ---- O += P V ----
        #pragma unroll
        for (int s2 = 0; s2 < 8; s2++) {
            uint32_t aP[4];
            aP[0] = __float_as_uint(Pw[g * LDP + s2*8 + th]);
            aP[1] = __float_as_uint(Pw[(g + 8) * LDP + s2*8 + th]);
            aP[2] = __float_as_uint(Pw[g * LDP + s2*8 + th + 4]);
            aP[3] = __float_as_uint(Pw[(g + 8) * LDP + s2*8 + th + 4]);
            #pragma unroll
            for (int nb2 = 0; nb2 < 8; nb2++) {
                const float* vrow = &Vs[(nb2*8 + g) * LDV];
                uint2 vb = *(const uint2*)&vrow[s2*8 + 2*th];
                mma16n8k8(oacc[nb2], aP, vb.x, vb.y);
            }
        }
        __syncthreads();   // all reads of buf done before refill
    }

    l0 += __shfl_xor_sync(0xffffffffu, l0, 1);
    l0 += __shfl_xor_sync(0xffffffffu, l0, 2);
    l1 += __shfl_xor_sync(0xffffffffu, l1, 1);
    l1 += __shfl_xor_sync(0xffffffffu, l1, 2);
    float inv[2] = {1.f / l0, 1.f / l1};

    // scatter to ORIGINAL rows via perm
    #pragma unroll
    for (int rr = 0; rr < 2; rr++) {
        int srow = wr + g + rr*8;
        int orow = g_perm[b * TT + srow];
        float* d = g_Y + ((size_t)(b * TT + orow)) * D_ + h * HD;
        #pragma unroll
        for (int nb2 = 0; nb2 < 8; nb2++) {
            int c = nb2*8 + 2*th;
            *(uint2*)&d[c] = make_uint2(f2tf32(oacc[nb2][rr*2+0] * inv[rr]),
                                        f2tf32(oacc[nb2][rr*2+1] * inv[rr]));
        }
    }
}

// ============================================================================
// Proj GEMM (unchanged): A = g_Y natural, B = W_proj^T LDS.64.
// ============================================================================
__global__ __launch_bounds__(256, 2) void proj_mma(
    const float* __restrict__ bias, float* __restrict__ out)
{
    extern __shared__ float smf[];
    const uint32_t sbU = smem_u32(smf);

    const int tid  = threadIdx.x;
    const int wid  = tid >> 5, lane = tid & 31;
    const int g = lane >> 2, th = lane & 3;
    const int wm = wid & 3, wn = wid >> 2;
    const int m0 = blockIdx.y * 128, n0 = blockIdx.x * 128;

    auto stage = [&](int k0, int buf) {
        const uint32_t adst = sbU + (buf ? (uint32_t)(SLABF*4) : 0u);
        const uint32_t bdst = adst + TILEF*4;
        #pragma unroll
        for (int i = 0; i < 4; i++) {
            int cid = tid + i * 256;
            int r = cid >> 3, c = cid & 7;
            cp16(adst + (r*LDA + c*4)*4, g_Y + (size_t)(m0 + r)*512 + k0 + c*4);
        }
        #pragma unroll
        for (int i = 0; i < 4; i++) {
            int cid = tid + i * 256;
            int r = cid >> 3, c = cid & 7;
            cp16(bdst + (r*LDA + c*4)*4, g_WpT + (size_t)(n0 + r)*512 + k0 + c*4);
        }
        CP_COMMIT();
    };

    float acc[2][8][4];
    #pragma unroll
    for (int mt = 0; mt < 2; mt++)
        #pragma unroll
        for (int nt = 0; nt < 8; nt++)
            #pragma unroll
            for (int j = 0; j < 4; j++) acc[mt][nt][j] = 0.f;

    stage(0, 0);
    #pragma unroll 1
    for (int it = 0; it < 16; it++) {
        const int buf = it & 1;
        if (it < 15) { stage((it + 1) * 32, buf ^ 1); CP_WAIT(1); }
        else         { CP_WAIT(0); }
        __syncthreads();

        const float* As = smf + (buf ? SLABF : 0);
        const float* Bs = As + TILEF;

        #pragma unroll
        for (int s = 0; s < 4; s++) {
            uint32_t aF[2][4];
            #pragma unroll
            for (int mt = 0; mt < 2; mt++) {
                int rb = wm * 32 + mt * 16 + g;
                aF[mt][0] = __float_as_uint(As[rb * LDA + s*8 + th]);
                aF[mt][1] = __float_as_uint(As[(rb + 8) * LDA + s*8 + th]);
                aF[mt][2] = __float_as_uint(As[rb * LDA + s*8 + th + 4]);
                aF[mt][3] = __float_as_uint(As[(rb + 8) * LDA + s*8 + th + 4]);
            }
            #pragma unroll
            for (int nt = 0; nt < 8; nt++) {
                int nc = wn * 64 + nt * 8 + g;
                uint2 bb = *(const uint2*)&Bs[nc * LDA + s*8 + 2*th];
                mma16n8k8(acc[0][nt], aF[0], bb.x, bb.y);
                mma16n8k8(acc[1][nt], aF[1], bb.x, bb.y);
            }
        }
        __syncthreads();
    }

    #pragma unroll
    for (int mt = 0; mt < 2; mt++) {
        #pragma unroll
        for (int r2 = 0; r2 < 2; r2++) {
            int row = m0 + wm * 32 + mt * 16 + g + r2 * 8;
            int bb = row >> 11;
            int tt = row & 2047;
            size_t base = (tt < T_)
                ? ((size_t)(bb * T_ + tt) * D_)
                : ((size_t)B_ * T_ * D_ + (size_t)(bb * T_ + (tt - T_)) * D_);
            #pragma unroll
            for (int nt = 0; nt < 8; nt++) {
                int col = n0 + wn * 64 + nt * 8 + 2 * th;
                float2 v = make_float2(acc[mt][nt][r2*2+0] + bias[col],
                                       acc[mt][nt][r2*2+1] + bias[col+1]);
                *(float2*)&out[base + col] = v;
            }
        }
    }
}

// ---------------------------------------------------------------------------
extern "C" void kernel_launch(void* const* d_in, const int* in_sizes, int n_in,
                              void* d_out, int out_size)
{
    const float* self_seq  = (const float*)d_in[0];
    const float* cross_seq = (const float*)d_in[1];
    const int*   t_self    = (const int*)d_in[2];
    const int*   t_cross   = (const int*)d_in[3];
    const float* W_self    = (const float*)d_in[4];
    const float* b_self    = (const float*)d_in[5];
    const float* W_cross   = (const float*)d_in[6];
    const float* b_cross   = (const float*)d_in[7];
    const float* W_proj    = (const float*)d_in[8];
    const float* b_proj    = (const float*)d_in[9];
    float* out = (float*)d_out;

    cudaFuncSetAttribute(attn_mma,
                         cudaFuncAttributeMaxDynamicSharedMemorySize, ATTN_SMEM);
    cudaFuncSetAttribute(qkv_mma,
                         cudaFuncAttributeMaxDynamicSharedMemorySize, GEMM_SMEM);
    cudaFuncSetAttribute(proj_mma,
                         cudaFuncAttributeMaxDynamicSharedMemorySize, GEMM_SMEM);

    prepass<<<PB_TOT, 256>>>(t_self, t_cross, self_seq, cross_seq,
                             W_self, W_cross, W_proj);

    qkv_mma<<<QKV_CTAS, 256, GEMM_SMEM>>>(b_self, b_cross);

    attn_mma<<<dim3(16, 32), 256, ATTN_SMEM>>>();

    proj_mma<<<dim3(4, 64), 256, GEMM_SMEM>>>(b_proj, out);
}

// round 17
// speedup vs baseline: 1.3889x; 1.0106x over previous
#include <cuda_runtime.h>
#include <cstdint>

#define B_  4
#define T_  1024
#define TT  2048
#define D_  512
#define H_  8
#define HD  64

// Scratch (allocation-free rule: __device__ globals).
__device__ float g_Q[B_*H_*TT*HD];     // tf32 (b,h,pos,hd), pos = time-sorted
__device__ float g_K[B_*H_*TT*HD];     // tf32 (b,h,pos,hd), hd ilv8, sorted
__device__ float g_Vt[B_*H_*HD*TT];    // tf32 V^T (b,h,hd,pos), pos ilv8, sorted
__device__ float g_Y[B_*TT*D_];        // attn out, tf32, (b,t,d) ORIGINAL order
__device__ float g_rXs[B_*T_*D_];      // tf32, k ilv8
__device__ float g_rXc[B_*T_*D_];
__device__ float g_WsT[3*D_*D_];       // W^T (n,k), tf32, k ilv8
__device__ float g_WcT[3*D_*D_];
__device__ float g_WpT[D_*D_];
// time-sort outputs
__device__ int g_sortT[B_*TT];
__device__ int g_perm[B_*TT];
__device__ int g_rank[B_*TT];

__device__ __forceinline__ uint32_t f2tf32(float x) {
    uint32_t r;
    asm("cvt.rna.tf32.f32 %0, %1;" : "=r"(r) : "f"(x));
    return r;
}
__device__ __forceinline__ float fexp2(float x) {
    float y;
    asm("ex2.approx.f32 %0, %1;" : "=f"(y) : "f"(x));
    return y;
}
__device__ __forceinline__ int ilv8(int k) {
    return (k & ~7) | ((k & 3) << 1) | ((k & 4) >> 2);
}
__device__ __forceinline__ void mma16n8k8(float* c, const uint32_t* a,
                                          uint32_t b0, uint32_t b1) {
    asm volatile(
        "mma.sync.aligned.m16n8k8.row.col.f32.tf32.tf32.f32 "
        "{%0,%1,%2,%3}, {%4,%5,%6,%7}, {%8,%9}, {%0,%1,%2,%3};"
        : "+f"(c[0]), "+f"(c[1]), "+f"(c[2]), "+f"(c[3])
        : "r"(a[0]), "r"(a[1]), "r"(a[2]), "r"(a[3]), "r"(b0), "r"(b1));
}
__device__ __forceinline__ void cp16(uint32_t dst, const void* src) {
    asm volatile("cp.async.cg.shared.global [%0], [%1], 16;"
                 :: "r"(dst), "l"(src) : "memory");
}
#define CP_COMMIT() asm volatile("cp.async.commit_group;" ::: "memory")
#define CP_WAIT(n)  asm volatile("cp.async.wait_group %0;" :: "n"(n) : "memory")
__device__ __forceinline__ uint32_t smem_u32(const void* p) {
    uint32_t a;
    asm("{ .reg .u64 t; cvta.to.shared.u64 t, %1; cvt.u32.u64 %0, t; }"
        : "=r"(a) : "l"(p));
    return a;
}

// ============================================================================
// Fused pre-pass (single launch; each block takes exactly one branch).
// ============================================================================
#define NX8 (B_*T_*D_/8)
#define PB_SORT 4
#define PB_RX   2048
#define PB_WT   2304
#define PB_TOT  (PB_SORT + PB_RX + PB_WT)

__global__ __launch_bounds__(256) void prepass(
    const int* __restrict__ t_self, const int* __restrict__ t_cross,
    const float* __restrict__ Xs, const float* __restrict__ Xc,
    const float* __restrict__ Ws, const float* __restrict__ Wc,
    const float* __restrict__ Wp)
{
    __shared__ int st[2048];
    __shared__ int sp[2048];
    const int bx  = blockIdx.x;
    const int tid = threadIdx.x;

    if (bx < PB_SORT) {
        const int b = bx;
        for (int i = tid; i < 2048; i += 256) {
            st[i] = (i < T_) ? t_self[b*T_ + i] : t_cross[b*T_ + i - T_];
            sp[i] = i;
        }
        __syncthreads();
        for (int k = 2; k <= 2048; k <<= 1) {
            for (int j = k >> 1; j > 0; j >>= 1) {
                for (int i = tid; i < 2048; i += 256) {
                    int ixj = i ^ j;
                    if (ixj > i) {
                        bool up = ((i & k) == 0);
                        int t1 = st[i], t2 = st[ixj];
                        int p1 = sp[i], p2 = sp[ixj];
                        bool gt = (t1 > t2) || (t1 == t2 && p1 > p2);
                        if (gt == up) {
                            st[i] = t2; st[ixj] = t1;
                            sp[i] = p2; sp[ixj] = p1;
                        }
                    }
                }
                __syncthreads();
            }
        }
        for (int i = tid; i < 2048; i += 256) {
            g_sortT[b*TT + i] = st[i];
            g_perm[b*TT + i]  = sp[i];
            g_rank[b*TT + sp[i]] = i;
        }
    } else if (bx < PB_SORT + PB_RX) {
        int i = (bx - PB_SORT) * 256 + tid;
        if (i >= 2 * NX8) return;
        const float4* src = (i < NX8) ? (const float4*)Xs : (const float4*)Xc;
        float4* dst       = (i < NX8) ? (float4*)g_rXs    : (float4*)g_rXc;
        int j = (i < NX8) ? i : i - NX8;
        float4 a = src[2*j], b = src[2*j + 1];
        uint4 o0 = make_uint4(f2tf32(a.x), f2tf32(b.x), f2tf32(a.y), f2tf32(b.y));
        uint4 o1 = make_uint4(f2tf32(a.z), f2tf32(b.z), f2tf32(a.w), f2tf32(b.w));
        ((uint4*)dst)[2*j]     = o0;
        ((uint4*)dst)[2*j + 1] = o1;
    } else {
        int flat = bx - PB_SORT - PB_RX;
        const int z  = flat / 768;
        const int r6 = flat % 768;
        const int kb = (r6 & 15) * 32;
        const int nby = r6 >> 4;
        if (z == 2 && nby >= 16) return;
        const int nb = nby * 32;
        const float* W = (z == 0) ? Ws : (z == 1) ? Wc : Wp;
        float* WT      = (z == 0) ? g_WsT : (z == 1) ? g_WcT : g_WpT;
        const int N = (z == 2) ? 512 : 1536;

        float* smw = (float*)st;
        #pragma unroll
        for (int i = tid; i < 1024; i += 256) {
            int r = i >> 5, c = i & 31;
            smw[r * 33 + c] = W[(size_t)(kb + r) * N + nb + c];
        }
        __syncthreads();
        #pragma unroll
        for (int i = tid; i < 1024; i += 256) {
            int nl = i >> 5, kp = i & 31;
            int klog = (kp & ~7) | ((kp & 1) << 2) | ((kp >> 1) & 3);
            WT[(size_t)(nb + nl) * 512 + kb + kp] =
                __uint_as_float(f2tf32(smw[klog * 33 + nl]));
        }
    }
}

// ============================================================================
// QKV GEMM, PERSISTENT (296 CTAs over 768 tiles). Scatter via g_rank.
// ============================================================================
#define LDA 40
#define TILEF (128*LDA)
#define SLABF (2*TILEF)
#define GEMM_SMEM (2*SLABF*4)
#define QKV_CTAS 296
#define QKV_TILES 768

__global__ __launch_bounds__(256, 2) void qkv_mma(
    const float* __restrict__ bS, const float* __restrict__ bC)
{
    extern __shared__ float smf[];
    const uint32_t sbU = smem_u32(smf);

    const int tid  = threadIdx.x;
    const int wid  = tid >> 5, lane = tid & 31;
    const int g = lane >> 2, th = lane & 3;
    const int wm = wid & 3, wn = wid >> 2;

    for (int tile = blockIdx.x; tile < QKV_TILES; tile += QKV_CTAS) {
        const int z  = tile >= 384;
        const int r  = tile - (z ? 384 : 0);
        const int m0 = (r / 12) * 128;
        const int n0 = (r % 12) * 128;
        const float* X    = z ? g_rXc : g_rXs;
        const float* WT   = z ? g_WcT : g_WsT;
        const float* bias = z ? bC : bS;
        const int seq_off = z ? 1024 : 0;

        auto stage = [&](int k0, int buf) {
            const uint32_t adst = sbU + (buf ? (uint32_t)(SLABF*4) : 0u);
            const uint32_t bdst = adst + TILEF*4;
            #pragma unroll
            for (int i = 0; i < 4; i++) {
                int cid = tid + i * 256;
                int rr = cid >> 3, c = cid & 7;
                cp16(adst + (rr*LDA + c*4)*4, X + (size_t)(m0 + rr)*512 + k0 + c*4);
            }
            #pragma unroll
            for (int i = 0; i < 4; i++) {
                int cid = tid + i * 256;
                int rr = cid >> 3, c = cid & 7;
                cp16(bdst + (rr*LDA + c*4)*4, WT + (size_t)(n0 + rr)*512 + k0 + c*4);
            }
            CP_COMMIT();
        };

        float acc[2][8][4];
        #pragma unroll
        for (int mt = 0; mt < 2; mt++)
            #pragma unroll
            for (int nt = 0; nt < 8; nt++)
                #pragma unroll
                for (int j = 0; j < 4; j++) acc[mt][nt][j] = 0.f;

        stage(0, 0);
        #pragma unroll 1
        for (int it = 0; it < 16; it++) {
            const int buf = it & 1;
            if (it < 15) { stage((it + 1) * 32, buf ^ 1); CP_WAIT(1); }
            else         { CP_WAIT(0); }
            __syncthreads();

            const float* As = smf + (buf ? SLABF : 0);
            const float* Bs = As + TILEF;

            #pragma unroll
            for (int s = 0; s < 4; s++) {
                uint32_t aF[2][4];
                #pragma unroll
                for (int mt = 0; mt < 2; mt++) {
                    int rb = wm * 32 + mt * 16 + g;
                    uint2 aLo = *(const uint2*)&As[rb * LDA + s*8 + 2*th];
                    uint2 aHi = *(const uint2*)&As[(rb + 8) * LDA + s*8 + 2*th];
                    aF[mt][0] = aLo.x; aF[mt][1] = aHi.x;
                    aF[mt][2] = aLo.y; aF[mt][3] = aHi.y;
                }
                #pragma unroll
                for (int nt = 0; nt < 8; nt++) {
                    int nc = wn * 64 + nt * 8 + g;
                    uint2 bb = *(const uint2*)&Bs[nc * LDA + s*8 + 2*th];
                    mma16n8k8(acc[0][nt], aF[0], bb.x, bb.y);
                    mma16n8k8(acc[1][nt], aF[1], bb.x, bb.y);
                }
            }
            __syncthreads();
        }

        #pragma unroll
        for (int mt = 0; mt < 2; mt++) {
            #pragma unroll
            for (int r2 = 0; r2 < 2; r2++) {
                int row = m0 + wm * 32 + mt * 16 + g + r2 * 8;
                int bb = row >> 10;
                int tg = (row & 1023) + seq_off;
                int pos = g_rank[bb * TT + tg];
                #pragma unroll
                for (int nt = 0; nt < 8; nt++) {
                    int col = n0 + wn * 64 + nt * 8 + 2 * th;
                    float v0 = acc[mt][nt][r2*2+0] + bias[col];
                    float v1 = acc[mt][nt][r2*2+1] + bias[col+1];
                    int sel = col >> 9, c = col & 511;
                    int h = c >> 6, dd = c & 63;
                    if (sel == 2) {
                        int tgp = (pos & ~7) | ((pos & 3) << 1) | ((pos & 4) >> 2);
                        float* dv = g_Vt + ((((size_t)bb * H_ + h) * HD + dd) * TT) + tgp;
                        dv[0]  = __uint_as_float(f2tf32(v0));
                        dv[TT] = __uint_as_float(f2tf32(v1));
                    } else if (sel == 1) {
                        size_t base = (((size_t)bb * H_ + h) * TT + pos) << 6;
                        g_K[base + ilv8(dd)]     = __uint_as_float(f2tf32(v0));
                        g_K[base + ilv8(dd + 1)] = __uint_as_float(f2tf32(v1));
                    } else {
                        size_t off = ((((size_t)bb * H_ + h) * TT + pos) << 6) + dd;
                        g_Q[off]     = __uint_as_float(f2tf32(v0));
                        g_Q[off + 1] = __uint_as_float(f2tf32(v1));
                    }
                }
            }
        }
        __syncthreads();   // buffers reused by next tile
    }
}

// ============================================================================
// Flash attention on time-sorted tokens (R16 config) with:
//   - CTA k-loop bounded by nkt (live tiles only)
//   - fully-live fast path (skip tks + mask SELs)
//   - NEW: fully-dead warp skip: tile min key-time > warp max query-time
//     => mask all-false for this warp => skip S/exp/P/PV entirely
//   - tks boundary loads as int2
// ============================================================================
#define KT  64
#define NKT 32
#define LDK 72
#define LDV 72
#define LDP 68
#define K0B 0
#define K1B 18432
#define V0B 36864
#define V1B 55296
#define PB  73728
#define T0B 108544
#define T1B 108800
#define ATTN_SMEM 109056

__global__ __launch_bounds__(256, 2) void attn_mma(void)
{
    extern __shared__ char smc[];
    const uint32_t sbU = smem_u32(smc);

    const int tid  = threadIdx.x;
    const int wid  = tid >> 5;
    const int lane = tid & 31;
    const int g    = lane >> 2;
    const int th   = lane & 3;
    const int bh   = blockIdx.y, b = bh >> 3, h = bh & 7;
    const int qt   = (int)(gridDim.x - 1) - (int)blockIdx.x;  // heavy first per bh
    const int q0   = qt * 128;

    const float* Qg = g_Q + (size_t)bh * TT * HD;
    const float* Kg = g_K + (size_t)bh * TT * HD;
    const float* Vg = g_Vt + (size_t)bh * HD * TT;
    const int* sT   = g_sortT + b * TT;

    const int maxtq = sT[q0 + 127];
    int nkt;
    {
        bool pred = (sT[lane << 6] <= maxtq);
        nkt = __popc(__ballot_sync(0xffffffffu, pred));
    }

    auto issue = [&](int kt, int bufsel) {
        const int k0 = kt * KT;
        const uint32_t kdst = sbU + (bufsel ? K1B : K0B);
        const uint32_t vdst = sbU + (bufsel ? V1B : V0B);
        #pragma unroll
        for (int i = 0; i < 4; i++) {
            int idx = tid + i * 256;
            int row = idx >> 4, c = idx & 15;
            cp16(kdst + row * (LDK*4) + c * 16,
                 Kg + (size_t)(k0 + row) * HD + c * 4);
        }
        #pragma unroll
        for (int i = 0; i < 4; i++) {
            int idx = tid + i * 256;
            int row = idx >> 4, c = idx & 15;
            cp16(vdst + row * (LDV*4) + c * 16,
                 Vg + (size_t)row * TT + k0 + c * 4);
        }
        if (tid < 16) {
            cp16(sbU + (bufsel ? T1B : T0B) + tid * 16, sT + k0 + tid * 4);
        }
        CP_COMMIT();
    };
    issue(0, 0);

    const int wr = q0 + wid * 16;
    const int wmin = sT[wr];        // warp's min query time (rows ascending)
    const int wmax = sT[wr + 15];   // warp's max query time

    uint32_t aQ[8][4];
    {
        const float* qp0 = Qg + (size_t)(wr + g) * HD;
        const float* qp1 = Qg + (size_t)(wr + g + 8) * HD;
        #pragma unroll
        for (int s = 0; s < 8; s++) {
            aQ[s][0] = __float_as_uint(qp0[s*8 + th]);
            aQ[s][1] = __float_as_uint(qp1[s*8 + th]);
            aQ[s][2] = __float_as_uint(qp0[s*8 + th + 4]);
            aQ[s][3] = __float_as_uint(qp1[s*8 + th + 4]);
        }
    }
    int tq[2];
    #pragma unroll
    for (int rr = 0; rr < 2; rr++)
        tq[rr] = sT[wr + g + rr*8];

    float oacc[8][4];
    #pragma unroll
    for (int n = 0; n < 8; n++)
        #pragma unroll
        for (int j = 0; j < 4; j++) oacc[n][j] = 0.f;
    float l0 = 0.f, l1 = 0.f;

    float* Pw = (float*)(smc + PB) + wid * 16 * LDP;
    const float E = 0.125f * 1.44269504f;

    #pragma unroll 1
    for (int kt = 0; kt < nkt; kt++) {
        const int buf = kt & 1;
        if (kt < nkt - 1) { issue(kt + 1, buf ^ 1); CP_WAIT(1); }
        else              { CP_WAIT(0); }
        __syncthreads();

        const float* Ks  = (const float*)(smc + (buf ? K1B : K0B));
        const float* Vs  = (const float*)(smc + (buf ? V1B : V0B));
        const int*   tks = (const int*)(smc + (buf ? T1B : T0B));

        // fully dead for every row of this warp? (tile min > warp max)
        if (tks[0] > wmax) { __syncthreads(); continue; }
        // fully live for every row of this warp?
        const bool fullLive = (tks[63] <= wmin);

        // ---- S = Q K^T in nb-PAIRS (two independent MMA chains) ----
        #pragma unroll
        for (int nb = 0; nb < 8; nb += 2) {
            float sa0[4] = {0.f, 0.f, 0.f, 0.f};
            float sa1[4] = {0.f, 0.f, 0.f, 0.f};
            const float* kr0 = &Ks[(nb*8 + g) * LDK];
            const float* kr1 = &Ks[((nb+1)*8 + g) * LDK];
            #pragma unroll
            for (int s = 0; s < 8; s++) {
                uint2 k0v = *(const uint2*)&kr0[s*8 + 2*th];
                uint2 k1v = *(const uint2*)&kr1[s*8 + 2*th];
                mma16n8k8(sa0, aQ[s], k0v.x, k0v.y);
                mma16n8k8(sa1, aQ[s], k1v.x, k1v.y);
            }
            #pragma unroll
            for (int u = 0; u < 2; u++) {
                const float* sa = u ? sa1 : sa0;
                const int c0 = (nb + u)*8 + 2*th;
                float p00, p01, p10, p11;
                if (fullLive) {
                    p00 = fexp2(sa[0] * E);
                    p01 = fexp2(sa[1] * E);
                    p10 = fexp2(sa[2] * E);
                    p11 = fexp2(sa[3] * E);
                } else {
                    const int2 tkp = *(const int2*)&tks[c0];
                    p00 = (tq[0] >= tkp.x) ? fexp2(sa[0] * E) : 0.f;
                    p01 = (tq[0] >= tkp.y) ? fexp2(sa[1] * E) : 0.f;
                    p10 = (tq[1] >= tkp.x) ? fexp2(sa[2] * E) : 0.f;
                    p11 = (tq[1] >= tkp.y) ? fexp2(sa[3] * E) : 0.f;
                }
                l0 += p00 + p01;  l1 += p10 + p11;
                *(uint2*)&Pw[g * LDP + c0] =
                    make_uint2(f2tf32(p00), f2tf32(p01));
                *(uint2*)&Pw[(g + 8) * LDP + c0] =
                    make_uint2(f2tf32(p10), f2tf32(p11));
            }
        }
        __syncwarp();   // P is per-warp private

        // ---- O += P V ----
        #pragma unroll
        for (int s2 = 0; s2 < 8; s2++) {
            uint32_t aP[4];
            aP[0] = __float_as_uint(Pw[g * LDP + s2*8 + th]);
            aP[1] = __float_as_uint(Pw[(g + 8) * LDP + s2*8 + th]);
            aP[2] = __float_as_uint(Pw[g * LDP + s2*8 + th + 4]);
            aP[3] = __float_as_uint(Pw[(g + 8) * LDP + s2*8 + th + 4]);
            #pragma unroll
            for (int nb2 = 0; nb2 < 8; nb2++) {
                const float* vrow = &Vs[(nb2*8 + g) * LDV];
                uint2 vb = *(const uint2*)&vrow[s2*8 + 2*th];
                mma16n8k8(oacc[nb2], aP, vb.x, vb.y);
            }
        }
        __syncthreads();   // all reads of buf done before refill
    }

    l0 += __shfl_xor_sync(0xffffffffu, l0, 1);
    l0 += __shfl_xor_sync(0xffffffffu, l0, 2);
    l1 += __shfl_xor_sync(0xffffffffu, l1, 1);
    l1 += __shfl_xor_sync(0xffffffffu, l1, 2);
    float inv[2] = {1.f / l0, 1.f / l1};

    // scatter to ORIGINAL rows via perm
    #pragma unroll
    for (int rr = 0; rr < 2; rr++) {
        int srow = wr + g + rr*8;
        int orow = g_perm[b * TT + srow];
        float* d = g_Y + ((size_t)(b * TT + orow)) * D_ + h * HD;
        #pragma unroll
        for (int nb2 = 0; nb2 < 8; nb2++) {
            int c = nb2*8 + 2*th;
            *(uint2*)&d[c] = make_uint2(f2tf32(oacc[nb2][rr*2+0] * inv[rr]),
                                        f2tf32(oacc[nb2][rr*2+1] * inv[rr]));
        }
    }
}

// ============================================================================
// Proj GEMM (unchanged): A = g_Y natural, B = W_proj^T LDS.64.
// ============================================================================
__global__ __launch_bounds__(256, 2) void proj_mma(
    const float* __restrict__ bias, float* __restrict__ out)
{
    extern __shared__ float smf[];
    const uint32_t sbU = smem_u32(smf);

    const int tid  = threadIdx.x;
    const int wid  = tid >> 5, lane = tid & 31;
    const int g = lane >> 2, th = lane & 3;
    const int wm = wid & 3, wn = wid >> 2;
    const int m0 = blockIdx.y * 128, n0 = blockIdx.x * 128;

    auto stage = [&](int k0, int buf) {
        const uint32_t adst = sbU + (buf ? (uint32_t)(SLABF*4) : 0u);
        const uint32_t bdst = adst + TILEF*4;
        #pragma unroll
        for (int i = 0; i < 4; i++) {
            int cid = tid + i * 256;
            int r = cid >> 3, c = cid & 7;
            cp16(adst + (r*LDA + c*4)*4, g_Y + (size_t)(m0 + r)*512 + k0 + c*4);
        }
        #pragma unroll
        for (int i = 0; i < 4; i++) {
            int cid = tid + i * 256;
            int r = cid >> 3, c = cid & 7;
            cp16(bdst + (r*LDA + c*4)*4, g_WpT + (size_t)(n0 + r)*512 + k0 + c*4);
        }
        CP_COMMIT();
    };

    float acc[2][8][4];
    #pragma unroll
    for (int mt = 0; mt < 2; mt++)
        #pragma unroll
        for (int nt = 0; nt < 8; nt++)
            #pragma unroll
            for (int j = 0; j < 4; j++) acc[mt][nt][j] = 0.f;

    stage(0, 0);
    #pragma unroll 1
    for (int it = 0; it < 16; it++) {
        const int buf = it & 1;
        if (it < 15) { stage((it + 1) * 32, buf ^ 1); CP_WAIT(1); }
        else         { CP_WAIT(0); }
        __syncthreads();

        const float* As = smf + (buf ? SLABF : 0);
        const float* Bs = As + TILEF;

        #pragma unroll
        for (int s = 0; s < 4; s++) {
            uint32_t aF[2][4];
            #pragma unroll
            for (int mt = 0; mt < 2; mt++) {
                int rb = wm * 32 + mt * 16 + g;
                aF[mt][0] = __float_as_uint(As[rb * LDA + s*8 + th]);
                aF[mt][1] = __float_as_uint(As[(rb + 8) * LDA + s*8 + th]);
                aF[mt][2] = __float_as_uint(As[rb * LDA + s*8 + th + 4]);
                aF[mt][3] = __float_as_uint(As[(rb + 8) * LDA + s*8 + th + 4]);
            }
            #pragma unroll
            for (int nt = 0; nt < 8; nt++) {
                int nc = wn * 64 + nt * 8 + g;
                uint2 bb = *(const uint2*)&Bs[nc * LDA + s*8 + 2*th];
                mma16n8k8(acc[0][nt], aF[0], bb.x, bb.y);
                mma16n8k8(acc[1][nt], aF[1], bb.x, bb.y);
            }
        }
        __syncthreads();
    }

    #pragma unroll
    for (int mt = 0; mt < 2; mt++) {
        #pragma unroll
        for (int r2 = 0; r2 < 2; r2++) {
            int row = m0 + wm * 32 + mt * 16 + g + r2 * 8;
            int bb = row >> 11;
            int tt = row & 2047;
            size_t base = (tt < T_)
                ? ((size_t)(bb * T_ + tt) * D_)
                : ((size_t)B_ * T_ * D_ + (size_t)(bb * T_ + (tt - T_)) * D_);
            #pragma unroll
            for (int nt = 0; nt < 8; nt++) {
                int col = n0 + wn * 64 + nt * 8 + 2 * th;
                float2 v = make_float2(acc[mt][nt][r2*2+0] + bias[col],
                                       acc[mt][nt][r2*2+1] + bias[col+1]);
                *(float2*)&out[base + col] = v;
            }
        }
    }
}

// ---------------------------------------------------------------------------
extern "C" void kernel_launch(void* const* d_in, const int* in_sizes, int n_in,
                              void* d_out, int out_size)
{
    const float* self_seq  = (const float*)d_in[0];
    const float* cross_seq = (const float*)d_in[1];
    const int*   t_self    = (const int*)d_in[2];
    const int*   t_cross   = (const int*)d_in[3];
    const float* W_self    = (const float*)d_in[4];
    const float* b_self    = (const float*)d_in[5];
    const float* W_cross   = (const float*)d_in[6];
    const float* b_cross   = (const float*)d_in[7];
    const float* W_proj    = (const float*)d_in[8];
    const float* b_proj    = (const float*)d_in[9];
    float* out = (float*)d_out;

    cudaFuncSetAttribute(attn_mma,
                         cudaFuncAttributeMaxDynamicSharedMemorySize, ATTN_SMEM);
    cudaFuncSetAttribute(qkv_mma,
                         cudaFuncAttributeMaxDynamicSharedMemorySize, GEMM_SMEM);
    cudaFuncSetAttribute(proj_mma,
                         cudaFuncAttributeMaxDynamicSharedMemorySize, GEMM_SMEM);

    prepass<<<PB_TOT, 256>>>(t_self, t_cross, self_seq, cross_seq,
                             W_self, W_cross, W_proj);

    qkv_mma<<<QKV_CTAS, 256, GEMM_SMEM>>>(b_self, b_cross);

    attn_mma<<<dim3(16, 32), 256, ATTN_SMEM>>>();

    proj_mma<<<dim3(4, 64), 256, GEMM_SMEM>>>(b_proj, out);
}